// round 12
// baseline (speedup 1.0000x reference)
#include <cuda_runtime.h>
#include <cuda_bf16.h>
#include <math.h>

#define TT    512
#define BB    64
#define DD    1024
#define AA    128
#define AIN   2176           // D + D + A
#define KT1   2304           // composite K for stage1
#define NL    2
#define NCTA  256
#define NTHR  256
#define NG4   4096           // 4 gates * D
#define S1KC  16             // stage1 K-splits (144 k each)
#define SMEM_BYTES 69648     // 69632 payload + flag word

// ---------------- fp32 persistent state -------------------------------------
__device__ float s_ac[NL][BB * AA];
__device__ float s_fh[2][NL][BB * DD];
__device__ float s_fc[NL][BB * DD];
__device__ float s_p2[BB * NG4];             // interleaved: [m][col*4+g]
__device__ float s_p3[BB * NG4];
__device__ float s_b4[BB * NG4];
__device__ float s_pt[2][4][BB][NG4];        // stage3 partials, n'' = col*4+g
__device__ float s_pt1[S1KC][BB][512];       // stage1 partials, n' = j*4+c

// monotonic completion counters (zero-init at module load; mod-N detects last)
__device__ unsigned g_c1[8];
__device__ unsigned g_c3[32];

// ---------------- bf16 split state / operands -------------------------------
__device__ __align__(16) __nv_bfloat16 g_ahh[2][NL][BB * AA];
__device__ __align__(16) __nv_bfloat16 g_ahl[2][NL][BB * AA];
__device__ __align__(16) __nv_bfloat16 g_fhh[2][NL][BB * DD];
__device__ __align__(16) __nv_bfloat16 g_fhl[2][NL][BB * DD];
__device__ __align__(16) __nv_bfloat16 g_xph[BB * DD];
__device__ __align__(16) __nv_bfloat16 g_xpl[BB * DD];
__device__ __align__(16) __nv_bfloat16 g_hph[BB * DD];
__device__ __align__(16) __nv_bfloat16 g_hpl[BB * DD];
// pre-split inputs/weights (built once per replay)
__device__ __align__(16) __nv_bfloat16 g_xh[TT * BB * DD];
__device__ __align__(16) __nv_bfloat16 g_xl[TT * BB * DD];
__device__ __align__(16) __nv_bfloat16 g_w1h[2][512 * KT1];   // rows in n' order
__device__ __align__(16) __nv_bfloat16 g_w1l[2][512 * KT1];
__device__ __align__(16) __nv_bfloat16 g_pwh[2][14336 * 128];
__device__ __align__(16) __nv_bfloat16 g_pwl[2][14336 * 128];
__device__ __align__(16) __nv_bfloat16 g_wh[2][2][NG4 * DD];  // rows in n'' order
__device__ __align__(16) __nv_bfloat16 g_wl[2][2][NG4 * DD];

// ---------------- cp.async / mma helpers -------------------------------------
__device__ __forceinline__ void cp16(void* dst, const void* src) {
    unsigned d = (unsigned)__cvta_generic_to_shared(dst);
    asm volatile("cp.async.cg.shared.global [%0], [%1], 16;" :: "r"(d), "l"(src));
}
__device__ __forceinline__ void cp16w(void* dst, const void* src) {
    unsigned d = (unsigned)__cvta_generic_to_shared(dst);
    asm volatile("cp.async.ca.shared.global [%0], [%1], 16;" :: "r"(d), "l"(src));
}
__device__ __forceinline__ void cp_commit() {
    asm volatile("cp.async.commit_group;" ::: "memory");
}
__device__ __forceinline__ void cp_wait0() {
    asm volatile("cp.async.wait_group 0;" ::: "memory");
}
__device__ __forceinline__ void cp_wait1() {
    asm volatile("cp.async.wait_group 1;" ::: "memory");
}
__device__ __forceinline__ void ldsm4(unsigned r[4], unsigned addr) {
    asm volatile("ldmatrix.sync.aligned.m8n8.x4.shared.b16 {%0,%1,%2,%3}, [%4];"
                 : "=r"(r[0]), "=r"(r[1]), "=r"(r[2]), "=r"(r[3]) : "r"(addr));
}
__device__ __forceinline__ void mma16816(float d[4], const unsigned a[4],
                                         unsigned b0, unsigned b1) {
    asm volatile(
        "mma.sync.aligned.m16n8k16.row.col.f32.bf16.bf16.f32 "
        "{%0,%1,%2,%3},{%4,%5,%6,%7},{%8,%9},{%0,%1,%2,%3};"
        : "+f"(d[0]), "+f"(d[1]), "+f"(d[2]), "+f"(d[3])
        : "r"(a[0]), "r"(a[1]), "r"(a[2]), "r"(a[3]), "r"(b0), "r"(b1));
}
__device__ __forceinline__ void mma_x3(float d[4], const unsigned ah[4],
                                       const unsigned al[4],
                                       unsigned bh0, unsigned bh1,
                                       unsigned bl0, unsigned bl1) {
    mma16816(d, ah, bh0, bh1);
    mma16816(d, ah, bl0, bl1);
    mma16816(d, al, bh0, bh1);
}
__device__ __forceinline__ float4 ldcg4(const float* p) {
    return __ldcg((const float4*)p);
}

// ---------------- fence-free release/acquire grid barrier --------------------
__device__ unsigned g_cnt2;
__device__ unsigned g_gen2;

__device__ __forceinline__ void grid_sync(unsigned& gen) {
    __syncthreads();
    if (threadIdx.x == 0) {
        unsigned old;
        asm volatile("atom.add.acq_rel.gpu.global.u32 %0, [%1], 1;"
                     : "=r"(old) : "l"(&g_cnt2) : "memory");
        unsigned target = gen + 1;
        if ((old & (NCTA - 1u)) == NCTA - 1u) {
            asm volatile("st.release.gpu.global.u32 [%0], %1;"
                         :: "l"(&g_gen2), "r"(target) : "memory");
        } else {
            unsigned v;
            do {
                __nanosleep(32);
                asm volatile("ld.acquire.gpu.global.u32 %0, [%1];"
                             : "=r"(v) : "l"(&g_gen2) : "memory");
            } while ((int)(v - target) < 0);
        }
    }
    gen += 1;
    __syncthreads();
}

// last-arriver detection: all CTA threads call; returns true in the CTA whose
// arrival completes the contributor group (release/acquire chain via counter).
__device__ __forceinline__ bool arrive_last(unsigned* ctr, unsigned mod, int* flag) {
    __syncthreads();                      // partial stores done CTA-wide
    if (threadIdx.x == 0) {
        unsigned old;
        asm volatile("atom.add.acq_rel.gpu.global.u32 %0, [%1], 1;"
                     : "=r"(old) : "l"(ctr) : "memory");
        *flag = ((old & (mod - 1u)) == mod - 1u) ? 1 : 0;
    }
    __syncthreads();
    return *flag != 0;
}

__device__ __forceinline__ float sigf(float x) { return 1.0f / (1.0f + expf(-x)); }
__device__ __forceinline__ void bsplit(float v, __nv_bfloat16* ph, __nv_bfloat16* pl) {
    __nv_bfloat16 h = __float2bfloat16(v);
    *ph = h;
    *pl = __float2bfloat16(v - __bfloat162float(h));
}

struct Params {
    const float* x;
    const float* awih[2]; const float* awhh[2];
    const float* abih[2]; const float* abhh[2];
    const float* pw[2];   const float* pb[2];
    const float* fwih[2]; const float* fwhh[2]; const float* fb[2];
    float* out;
};

// ============================ stage 1 GEMM + fused aLSTM cell ================
// 128 CTAs = 8 n-tiles(64 n' = 16 hidden j x 4 gates) x 16 k-splits.
// smem/buffer (halves): A_hi[64][56]@0, A_lo@3584, W_hi[64][56]@7168, W_lo@10752.
__device__ __forceinline__ void s1_fillA(
    int ch, __nv_bfloat16* buf, int kc,
    const __nv_bfloat16* __restrict__ xh, const __nv_bfloat16* __restrict__ xl,
    const __nv_bfloat16* __restrict__ fhh, const __nv_bfloat16* __restrict__ fhl,
    const __nv_bfloat16* __restrict__ aoh, const __nv_bfloat16* __restrict__ aol,
    const __nv_bfloat16* __restrict__ ash, const __nv_bfloat16* __restrict__ asl)
{
    const int tid = threadIdx.x;
    const int k0 = kc * 144 + ch * 48;
    #pragma unroll
    for (int r = 0; r < 3; r++) {
        int idx = r * 256 + tid;
        int part = idx >= 384 ? 1 : 0;
        int rem = idx - part * 384;
        int m = rem / 6, u = rem - m * 6;
        int k = k0 + u * 8;
        const __nv_bfloat16* s;
        if (k < DD)            s = (part ? xl : xh) + m * DD + k;
        else if (k < 2 * DD)   s = (part ? fhl : fhh) + m * DD + (k - DD);
        else if (k < AIN)      s = (part ? aol : aoh) + m * AA + (k - 2 * DD);
        else                   s = (part ? asl : ash) + m * AA + (k - AIN);
        cp16(buf + part * 3584 + m * 56 + u * 8, s);
    }
}

__device__ __forceinline__ void s1_fillW(
    int ch, __nv_bfloat16* buf, int kc, int n0,
    const __nv_bfloat16* __restrict__ wh, const __nv_bfloat16* __restrict__ wl)
{
    const int tid = threadIdx.x;
    const int k0 = kc * 144 + ch * 48;
    #pragma unroll
    for (int r = 0; r < 3; r++) {
        int idx = r * 256 + tid;
        int part = idx >= 384 ? 1 : 0;
        int rem = idx - part * 384;
        int n = rem / 6, u = rem - n * 6;
        cp16w(buf + 7168 + part * 3584 + n * 56 + u * 8,
              (part ? wl : wh) + (size_t)(n0 + n) * KT1 + k0 + u * 8);
    }
}

__device__ __forceinline__ void s1_prefetchW(int l, __nv_bfloat16* sm)
{
    const int b = blockIdx.x;
    if (b >= 128) return;
    const int nt = b >> 4, kc = b & 15;
    s1_fillW(0, sm, kc, nt * 64, g_w1h[l], g_w1l[l]);
    cp_commit();
}

__device__ __forceinline__ void stage1_gemm(
    int l, int p, __nv_bfloat16* sm,
    const __nv_bfloat16* xh, const __nv_bfloat16* xl,
    const float* __restrict__ abih, const float* __restrict__ abhh)
{
    const int tid = threadIdx.x, b = blockIdx.x;
    if (b >= 128) return;
    const int nt = b >> 4, kc = b & 15;
    const int n0 = nt * 64;
    int* flag = (int*)(sm + 34816);

    const __nv_bfloat16* fhh = g_fhh[p][l];
    const __nv_bfloat16* fhl = g_fhl[p][l];
    const __nv_bfloat16* aoh = (l == 0) ? g_ahh[p][1] : g_ahh[p ^ 1][0];
    const __nv_bfloat16* aol = (l == 0) ? g_ahl[p][1] : g_ahl[p ^ 1][0];
    const __nv_bfloat16* ash = g_ahh[p][l];
    const __nv_bfloat16* asl = g_ahl[p][l];
    const __nv_bfloat16* wh = g_w1h[l];
    const __nv_bfloat16* wl = g_w1l[l];

    const int w = tid >> 5, lane = tid & 31;
    const int wm = w & 1, wn = w >> 1;
    const int g = lane >> 2, t4 = lane & 3;
    const int tA = lane >> 3;
    const int arow = (tA & 1) * 8 + (lane & 7), acol = (tA >> 1) * 8;
    const int brow = (lane >> 4) * 8 + (lane & 7), bcol = ((lane >> 3) & 1) * 8;
    const unsigned base0 = (unsigned)__cvta_generic_to_shared(sm);

    float D[2][2][4];
    #pragma unroll
    for (int im = 0; im < 2; im++)
        #pragma unroll
        for (int q = 0; q < 2; q++)
            D[im][q][0] = D[im][q][1] = D[im][q][2] = D[im][q][3] = 0.f;

    s1_fillA(0, sm, kc, xh, xl, fhh, fhl, aoh, aol, ash, asl);
    cp_commit();

    for (int ch = 0; ch < 3; ch++) {
        if (ch < 2) {
            __nv_bfloat16* nb = sm + ((ch + 1) & 1) * 14336;
            s1_fillA(ch + 1, nb, kc, xh, xl, fhh, fhl, aoh, aol, ash, asl);
            s1_fillW(ch + 1, nb, kc, n0, wh, wl);
            cp_commit();
            cp_wait1();
        } else {
            cp_wait0();
        }
        __syncthreads();
        const unsigned bufB = base0 + (unsigned)((ch & 1) * 14336 * 2);
        #pragma unroll
        for (int ck = 0; ck < 3; ck++) {
            const int kadd = ck * 16;
            unsigned ah[2][4], al[2][4];
            #pragma unroll
            for (int im = 0; im < 2; im++) {
                unsigned a = bufB + 2u * ((wm * 32 + im * 16 + arow) * 56 + kadd + acol);
                ldsm4(ah[im], a);
                ldsm4(al[im], a + 2u * 3584);
            }
            unsigned bh[4], bl[4];
            {
                unsigned a = bufB + 2u * (7168 + (wn * 16 + brow) * 56 + kadd + bcol);
                ldsm4(bh, a);
                ldsm4(bl, a + 2u * 3584);
            }
            #pragma unroll
            for (int im = 0; im < 2; im++)
                #pragma unroll
                for (int q = 0; q < 2; q++)
                    mma_x3(D[im][q], ah[im], al[im],
                           bh[q * 2], bh[q * 2 + 1], bl[q * 2], bl[q * 2 + 1]);
        }
        __syncthreads();
    }

    #pragma unroll
    for (int im = 0; im < 2; im++) {
        int m0 = wm * 32 + im * 16 + g;
        #pragma unroll
        for (int q = 0; q < 2; q++) {
            int col = n0 + wn * 16 + q * 8 + 2 * t4;
            *(float2*)&s_pt1[kc][m0][col]     = make_float2(D[im][q][0], D[im][q][1]);
            *(float2*)&s_pt1[kc][m0 + 8][col] = make_float2(D[im][q][2], D[im][q][3]);
        }
    }

    // -------- fused aLSTM pointwise (last of the 16 kc contributors) --------
    if (arrive_last(&g_c1[nt], S1KC, flag)) {
        const int j0 = nt * 16;
        #pragma unroll
        for (int cell = 0; cell < 4; cell++) {
            int idx = cell * 256 + tid;
            int jl = idx & 15, m = idx >> 4;
            int j = j0 + jl;
            float4 acc = make_float4(0.f, 0.f, 0.f, 0.f);
            #pragma unroll
            for (int k = 0; k < S1KC; k++) {
                float4 v = ldcg4(&s_pt1[k][m][j * 4]);
                acc.x += v.x; acc.y += v.y; acc.z += v.z; acc.w += v.w;
            }
            float gi = acc.x + abih[0 * 128 + j] + abhh[0 * 128 + j];
            float gf = acc.y + abih[1 * 128 + j] + abhh[1 * 128 + j];
            float gz = acc.z + abih[2 * 128 + j] + abhh[2 * 128 + j];
            float go = acc.w + abih[3 * 128 + j] + abhh[3 * 128 + j];
            float cO = __ldcg(&s_ac[l][m * AA + j]);
            float cN = sigf(gf) * cO + sigf(gi) * tanhf(gz);
            float h  = sigf(go) * tanhf(cN);
            s_ac[l][m * AA + j] = cN;
            bsplit(h, &g_ahh[p ^ 1][l][m * AA + j], &g_ahl[p ^ 1][l][m * AA + j]);
        }
    }
}

// ============================ stage 2 (tensor) ===============================
// smem halves: A_hi[64][136]@0, A_lo@8704, W_hi@17408, W_lo@26112.
__device__ __forceinline__ void s2_prefetchW(int l, __nv_bfloat16* sm)
{
    const int tid = threadIdx.x, b = blockIdx.x;
    if (b >= 224) return;
    const int n0 = b * 64;
    const __nv_bfloat16* pwh = g_pwh[l];
    const __nv_bfloat16* pwl = g_pwl[l];
    #pragma unroll
    for (int r = 0; r < 8; r++) {
        int idx = r * 256 + tid;
        int part = idx >> 10, rem = idx & 1023;
        int n = rem >> 4, u = rem & 15;
        cp16w(sm + 17408 + part * 8704 + n * 136 + u * 8,
              (part ? pwl : pwh) + (size_t)(n0 + n) * 128 + u * 8);
    }
    cp_commit();
}

__device__ __forceinline__ void s2_store(
    int seg, int m, int col, float v,
    const float* __restrict__ xc, const float* __restrict__ fhOld,
    const float* __restrict__ fb)
{
    if (seg == 0) {
        float xv = v * __ldcg(xc + m * DD + col);
        bsplit(xv, &g_xph[m * DD + col], &g_xpl[m * DD + col]);
    } else if (seg == 1) {
        int cc = col - DD;
        float hv = v * __ldcg(fhOld + m * DD + cc);
        bsplit(hv, &g_hph[m * DD + cc], &g_hpl[m * DD + cc]);
    } else if (seg < 6) {
        int n2 = col - 2 * DD;                       // g*DD + cc
        s_p2[m * NG4 + (n2 & 1023) * 4 + (n2 >> 10)] = v;
    } else if (seg < 10) {
        int n3 = col - 6 * DD;
        s_p3[m * NG4 + (n3 & 1023) * 4 + (n3 >> 10)] = v;
    } else {
        int n4 = col - 10 * DD;
        s_b4[m * NG4 + (n4 & 1023) * 4 + (n4 >> 10)] = v * fb[n4];
    }
}

__device__ __forceinline__ void stage2(
    int l, int p, const float* __restrict__ xc,
    const float* __restrict__ pb, const float* __restrict__ fb,
    __nv_bfloat16* sm)
{
    const int tid = threadIdx.x, b = blockIdx.x;
    if (b >= 224) return;
    const int n0 = b * 64;
    const float* fhOld = s_fh[p][l];
    const __nv_bfloat16* ahh = g_ahh[p ^ 1][l];
    const __nv_bfloat16* ahl = g_ahl[p ^ 1][l];

    #pragma unroll
    for (int r = 0; r < 8; r++) {            // A fill (W prefetched earlier)
        int idx = r * 256 + tid;
        int part = idx >> 10, rem = idx & 1023;
        int m = rem >> 4, u = rem & 15;
        cp16(sm + part * 8704 + m * 136 + u * 8,
             (part ? ahl : ahh) + m * 128 + u * 8);
    }
    cp_commit();

    const int w = tid >> 5, lane = tid & 31;
    const int wm = w & 1, wn = w >> 1;
    const int g = lane >> 2, t4 = lane & 3;
    const int tA = lane >> 3;
    const int arow = (tA & 1) * 8 + (lane & 7), acol = (tA >> 1) * 8;
    const int brow = (lane >> 4) * 8 + (lane & 7), bcol = ((lane >> 3) & 1) * 8;
    const unsigned base0 = (unsigned)__cvta_generic_to_shared(sm);

    float D[2][2][4];
    #pragma unroll
    for (int im = 0; im < 2; im++)
        #pragma unroll
        for (int q = 0; q < 2; q++)
            D[im][q][0] = D[im][q][1] = D[im][q][2] = D[im][q][3] = 0.f;

    cp_wait0();
    __syncthreads();

    #pragma unroll
    for (int k16 = 0; k16 < 8; k16++) {
        const int kadd = k16 * 16;
        unsigned ah[2][4], al[2][4];
        #pragma unroll
        for (int im = 0; im < 2; im++) {
            unsigned a = base0 + 2u * ((wm * 32 + im * 16 + arow) * 136 + kadd + acol);
            ldsm4(ah[im], a);
            ldsm4(al[im], a + 2u * 8704);
        }
        unsigned bh[4], bl[4];
        {
            unsigned a = base0 + 2u * (17408 + (wn * 16 + brow) * 136 + kadd + bcol);
            ldsm4(bh, a);
            ldsm4(bl, a + 2u * 8704);
        }
        #pragma unroll
        for (int im = 0; im < 2; im++)
            #pragma unroll
            for (int q = 0; q < 2; q++)
                mma_x3(D[im][q], ah[im], al[im],
                       bh[q * 2], bh[q * 2 + 1], bl[q * 2], bl[q * 2 + 1]);
    }
    __syncthreads();

    const int seg = n0 >> 10;
    #pragma unroll
    for (int im = 0; im < 2; im++) {
        int m0 = wm * 32 + im * 16 + g;
        #pragma unroll
        for (int q = 0; q < 2; q++) {
            int col = n0 + wn * 16 + q * 8 + 2 * t4;
            s2_store(seg, m0, col,     D[im][q][0] + pb[col],     xc, fhOld, fb);
            s2_store(seg, m0, col + 1, D[im][q][1] + pb[col + 1], xc, fhOld, fb);
            s2_store(seg, m0 + 8, col,     D[im][q][2] + pb[col],     xc, fhOld, fb);
            s2_store(seg, m0 + 8, col + 1, D[im][q][3] + pb[col + 1], xc, fhOld, fb);
        }
    }
}

// ============================ stage 3 GEMM + fused fast-LSTM cell ============
// 256 CTAs = 2 ph x 32 nt(128 n'' = 32 cols x 4 gates) x 4 kc(256 k).
// smem/buffer (halves): A_hi[64][40]@0, A_lo@2560, W_hi[128][40]@5120, W_lo@10240.
__device__ __forceinline__ void s3_fillA(
    int s, __nv_bfloat16* buf, int kb,
    const __nv_bfloat16* __restrict__ Ah, const __nv_bfloat16* __restrict__ Al)
{
    const int tid = threadIdx.x;
    const int k0 = kb + s * 32;
    #pragma unroll
    for (int r = 0; r < 2; r++) {
        int idx = r * 256 + tid;
        int part = idx >> 8, m = (idx >> 2) & 63, u = idx & 3;
        cp16(buf + part * 2560 + m * 40 + u * 8,
             (part ? Al : Ah) + m * DD + k0 + u * 8);
    }
}

__device__ __forceinline__ void s3_fillW(
    int s, __nv_bfloat16* buf, int kb, int n0,
    const __nv_bfloat16* __restrict__ Wh, const __nv_bfloat16* __restrict__ Wl)
{
    const int tid = threadIdx.x;
    const int k0 = kb + s * 32;
    #pragma unroll
    for (int r = 0; r < 4; r++) {
        int idx = r * 256 + tid;
        int part = idx >> 9, n = (idx >> 2) & 127, u = idx & 3;
        cp16w(buf + 5120 + part * 5120 + n * 40 + u * 8,
              (part ? Wl : Wh) + (size_t)(n0 + n) * DD + k0 + u * 8);
    }
}

__device__ __forceinline__ void s3_prefetchW(int l, __nv_bfloat16* sm)
{
    const int b = blockIdx.x;
    const int ph = b >> 7, nt = (b & 127) >> 2, kc = b & 3;
    s3_fillW(0, sm, kc * 256, nt * 128, g_wh[l][ph], g_wl[l][ph]);
    cp_commit();
}

__device__ __forceinline__ void stage3_gemm(
    int l, int p, int t, __nv_bfloat16* sm, float* __restrict__ out)
{
    const int tid = threadIdx.x, b = blockIdx.x;
    const int ph = b >> 7;
    const int nt = (b & 127) >> 2;
    const int kc = b & 3;
    const int n0 = nt * 128;
    const int kb = kc * 256;
    int* flag = (int*)(sm + 34816);

    const __nv_bfloat16* Ah = ph ? g_hph : g_xph;
    const __nv_bfloat16* Al = ph ? g_hpl : g_xpl;
    const __nv_bfloat16* Wh = g_wh[l][ph];
    const __nv_bfloat16* Wl = g_wl[l][ph];

    const int w = tid >> 5, lane = tid & 31;
    const int wm = w & 1, wn = w >> 1;
    const int g = lane >> 2, t4 = lane & 3;
    const int tA = lane >> 3;
    const int aoff = ((tA & 1) * 8 + (lane & 7)) * 40 + (tA >> 1) * 8;
    const int boff = ((lane >> 4) * 8 + (lane & 7)) * 40 + ((lane >> 3) & 1) * 8;
    const unsigned smemBase = (unsigned)__cvta_generic_to_shared(sm);

    float D[2][4][4];
    #pragma unroll
    for (int im = 0; im < 2; im++)
        #pragma unroll
        for (int q = 0; q < 4; q++)
            D[im][q][0] = D[im][q][1] = D[im][q][2] = D[im][q][3] = 0.f;

    s3_fillA(0, sm, kb, Ah, Al);
    cp_commit();

    for (int s = 0; s < 8; s++) {
        if (s < 7) {
            __nv_bfloat16* nb = sm + ((s + 1) & 1) * 15360;
            s3_fillA(s + 1, nb, kb, Ah, Al);
            s3_fillW(s + 1, nb, kb, n0, Wh, Wl);
            cp_commit();
            cp_wait1();
        } else {
            cp_wait0();
        }
        __syncthreads();
        const unsigned bufBase = smemBase + (unsigned)((s & 1) * 15360 * 2);
        #pragma unroll
        for (int ks = 0; ks < 2; ks++) {
            const unsigned kadd = ks * 16;
            unsigned ah[2][4], al[2][4];
            #pragma unroll
            for (int im = 0; im < 2; im++) {
                unsigned base = bufBase + 2u * ((wm * 32 + im * 16) * 40 + kadd + aoff);
                ldsm4(ah[im], base);
                ldsm4(al[im], base + 2u * 2560);
            }
            unsigned bh[2][4], bl[2][4];
            #pragma unroll
            for (int in2 = 0; in2 < 2; in2++) {
                unsigned base = bufBase + 2u * (5120 + (wn * 32 + in2 * 16) * 40 + kadd + boff);
                ldsm4(bh[in2], base);
                ldsm4(bl[in2], base + 2u * 5120);
            }
            #pragma unroll
            for (int im = 0; im < 2; im++)
                #pragma unroll
                for (int in8 = 0; in8 < 4; in8++) {
                    int in2 = in8 >> 1, o = (in8 & 1) * 2;
                    mma_x3(D[im][in8], ah[im], al[im],
                           bh[in2][o], bh[in2][o + 1], bl[in2][o], bl[in2][o + 1]);
                }
        }
        __syncthreads();
    }

    float* dst = &s_pt[ph][kc][0][0];
    #pragma unroll
    for (int im = 0; im < 2; im++) {
        int m0 = wm * 32 + im * 16 + g;
        #pragma unroll
        for (int in8 = 0; in8 < 4; in8++) {
            int col = n0 + wn * 32 + in8 * 8 + 2 * t4;
            *(float2*)(dst + (size_t)m0 * NG4 + col) =
                make_float2(D[im][in8][0], D[im][in8][1]);
            *(float2*)(dst + (size_t)(m0 + 8) * NG4 + col) =
                make_float2(D[im][in8][2], D[im][in8][3]);
        }
    }

    // -------- fused fast-LSTM pointwise (last of 8 contributors: 2ph x 4kc) --
    if (arrive_last(&g_c3[nt], 8u, flag)) {
        const int c0 = nt * 32;
        #pragma unroll
        for (int cell = 0; cell < 8; cell++) {
            int idx = cell * 256 + tid;
            int cl = idx & 31, m = idx >> 5;
            int col = c0 + cl;
            int n4 = col * 4;
            float4 ig = make_float4(0.f, 0.f, 0.f, 0.f);
            float4 hg = make_float4(0.f, 0.f, 0.f, 0.f);
            #pragma unroll
            for (int k = 0; k < 4; k++) {
                float4 v = ldcg4(&s_pt[0][k][m][n4]);
                ig.x += v.x; ig.y += v.y; ig.z += v.z; ig.w += v.w;
                float4 u = ldcg4(&s_pt[1][k][m][n4]);
                hg.x += u.x; hg.y += u.y; hg.z += u.z; hg.w += u.w;
            }
            float4 p2 = ldcg4(&s_p2[m * NG4 + n4]);
            float4 p3 = ldcg4(&s_p3[m * NG4 + n4]);
            float4 b4 = ldcg4(&s_b4[m * NG4 + n4]);
            float Gi = fmaf(ig.x, p2.x, b4.x) + hg.x * p3.x;
            float Gf = fmaf(ig.y, p2.y, b4.y) + hg.y * p3.y;
            float Gz = fmaf(ig.z, p2.z, b4.z) + hg.z * p3.z;
            float Go = fmaf(ig.w, p2.w, b4.w) + hg.w * p3.w;
            float cO = __ldcg(&s_fc[l][m * DD + col]);
            float cN = sigf(Gf) * cO + sigf(Gi) * tanhf(Gz);
            float h  = sigf(Go) * tanhf(cN);
            s_fc[l][m * DD + col] = cN;
            s_fh[p ^ 1][l][m * DD + col] = h;
            bsplit(h, &g_fhh[p ^ 1][l][m * DD + col],
                      &g_fhl[p ^ 1][l][m * DD + col]);
            if (l == 1) out[((size_t)t * BB + m) * DD + col] = h;
        }
    }
}

// ---------------- persistent kernel ----------------------------------------
__global__ void __launch_bounds__(NTHR, 2) alstm_persistent(Params P)
{
    extern __shared__ __align__(16) float smf[];
    __nv_bfloat16* sm = (__nv_bfloat16*)smf;
    const int tid = threadIdx.x, b = blockIdx.x;
    const int gtid = b * NTHR + tid, gsz = NCTA * NTHR;

    unsigned gen;
    asm volatile("ld.acquire.gpu.global.u32 %0, [%1];" : "=r"(gen) : "l"(&g_gen2));

    {   // zero recurrent state each replay
        float* z2 = &s_ac[0][0];
        for (int i = gtid; i < NL * BB * AA; i += gsz) z2[i] = 0.f;
        float* z3 = &s_fh[0][0][0];
        for (int i = gtid; i < 2 * NL * BB * DD; i += gsz) z3[i] = 0.f;
        float* z4 = &s_fc[0][0];
        for (int i = gtid; i < NL * BB * DD; i += gsz) z4[i] = 0.f;
        __nv_bfloat16* z5 = &g_ahh[0][0][0];
        __nv_bfloat16* z6 = &g_ahl[0][0][0];
        for (int i = gtid; i < 2 * NL * BB * AA; i += gsz) { z5[i] = __nv_bfloat16(0.f); z6[i] = __nv_bfloat16(0.f); }
        __nv_bfloat16* z7 = &g_fhh[0][0][0];
        __nv_bfloat16* z8 = &g_fhl[0][0][0];
        for (int i = gtid; i < 2 * NL * BB * DD; i += gsz) { z7[i] = __nv_bfloat16(0.f); z8[i] = __nv_bfloat16(0.f); }
    }
    {   // split x (whole sequence)
        const float4* s4 = (const float4*)P.x;
        for (int i = gtid; i < TT * BB * DD / 4; i += gsz) {
            float4 v = s4[i];
            float f[4] = {v.x, v.y, v.z, v.w};
            #pragma unroll
            for (int q = 0; q < 4; q++)
                bsplit(f[q], &g_xh[4 * i + q], &g_xl[4 * i + q]);
        }
    }
    {   // split stage3 weights, rows permuted to n'' = col*4+g
        const float* Wsrc[4] = {P.fwih[0], P.fwhh[0], P.fwih[1], P.fwhh[1]};
        #pragma unroll
        for (int mtx = 0; mtx < 4; mtx++) {
            const float4* s4 = (const float4*)Wsrc[mtx];
            __nv_bfloat16* dh = &g_wh[mtx >> 1][mtx & 1][0];
            __nv_bfloat16* dl = &g_wl[mtx >> 1][mtx & 1][0];
            for (int d = gtid; d < NG4 * DD / 4; d += gsz) {
                int nq = d >> 8, kq = d & 255;               // dest row n'', k-quad
                int orig = (nq & 3) * 1024 + (nq >> 2);      // orig row g*1024+col
                float4 v = s4[orig * 256 + kq];
                float f[4] = {v.x, v.y, v.z, v.w};
                #pragma unroll
                for (int q = 0; q < 4; q++)
                    bsplit(f[q], &dh[4 * d + q], &dl[4 * d + q]);
            }
        }
    }
    {   // split pw (no permutation)
        #pragma unroll
        for (int l = 0; l < 2; l++) {
            const float4* s4 = (const float4*)P.pw[l];
            for (int i = gtid; i < 14336 * 128 / 4; i += gsz) {
                float4 v = s4[i];
                float f[4] = {v.x, v.y, v.z, v.w};
                #pragma unroll
                for (int q = 0; q < 4; q++)
                    bsplit(f[q], &g_pwh[l][4 * i + q], &g_pwl[l][4 * i + q]);
            }
        }
    }
    {   // build composite stage1 weights, rows permuted to n' = j*4+c
        #pragma unroll
        for (int l = 0; l < 2; l++) {
            const float* wih = P.awih[l];
            const float* whh = P.awhh[l];
            for (int i = gtid; i < 512 * KT1; i += gsz) {
                int np = i / KT1, k = i - np * KT1;
                int n = (np & 3) * 128 + (np >> 2);          // orig row c*128+j
                float v = (k < AIN) ? wih[(size_t)n * AIN + k]
                                    : whh[n * AA + (k - AIN)];
                bsplit(v, &g_w1h[l][i], &g_w1l[l][i]);
            }
        }
    }
    grid_sync(gen);

    s1_prefetchW(0, sm);

    for (int t = 0; t < TT; t++) {
        const int p = t & 1;
        #pragma unroll
        for (int l = 0; l < NL; l++) {
            const __nv_bfloat16* xh = (l == 0) ? g_xh + (size_t)t * BB * DD
                                               : g_fhh[p ^ 1][0];
            const __nv_bfloat16* xl = (l == 0) ? g_xl + (size_t)t * BB * DD
                                               : g_fhl[p ^ 1][0];
            stage1_gemm(l, p, sm, xh, xl, P.abih[l], P.abhh[l]);
            s2_prefetchW(l, sm);
            grid_sync(gen);
            const float* xc = (l == 0) ? P.x + (size_t)t * BB * DD
                                       : s_fh[p ^ 1][0];
            stage2(l, p, xc, P.pb[l], P.fb[l], sm);
            s3_prefetchW(l, sm);
            grid_sync(gen);
            stage3_gemm(l, p, t, sm, P.out);
            s1_prefetchW(l ^ 1, sm);
            grid_sync(gen);
        }
    }
    cp_wait0();
}

// ---------------- host launch ----------------------------------------------
extern "C" void kernel_launch(void* const* d_in, const int* in_sizes, int n_in,
                              void* d_out, int out_size)
{
    Params P;
    P.x       = (const float*)d_in[0];
    P.awih[0] = (const float*)d_in[1];  P.awih[1] = (const float*)d_in[10];
    P.awhh[0] = (const float*)d_in[2];  P.awhh[1] = (const float*)d_in[11];
    P.abih[0] = (const float*)d_in[3];  P.abih[1] = (const float*)d_in[12];
    P.abhh[0] = (const float*)d_in[4];  P.abhh[1] = (const float*)d_in[13];
    P.pw[0]   = (const float*)d_in[5];  P.pw[1]   = (const float*)d_in[14];
    P.pb[0]   = (const float*)d_in[6];  P.pb[1]   = (const float*)d_in[15];
    P.fwih[0] = (const float*)d_in[7];  P.fwih[1] = (const float*)d_in[16];
    P.fwhh[0] = (const float*)d_in[8];  P.fwhh[1] = (const float*)d_in[17];
    P.fb[0]   = (const float*)d_in[9];  P.fb[1]   = (const float*)d_in[18];
    P.out     = (float*)d_out;

    cudaFuncSetAttribute(alstm_persistent,
                         cudaFuncAttributeMaxDynamicSharedMemorySize,
                         SMEM_BYTES);
    alstm_persistent<<<NCTA, NTHR, SMEM_BYTES>>>(P);
}

// round 13
// speedup vs baseline: 1.2487x; 1.2487x over previous
#include <cuda_runtime.h>
#include <cuda_bf16.h>
#include <math.h>

#define TT    512
#define BB    64
#define DD    1024
#define AA    128
#define AIN   2176           // D + D + A
#define KT1   2304           // composite K for stage1
#define NL    2
#define NCTA  128
#define NTHR  512
#define NG4   4096           // 4 gates * D
#define S1KC  16             // stage1 K-splits (144 k each)
#define S3KC  2              // stage3 K-splits (512 k each)
#define SMEM_BYTES 95744     // stage2: A 34816B + W 60928B

// ---------------- fp32 persistent state -------------------------------------
__device__ float s_ac[NL][BB * AA];
__device__ float s_fh[2][NL][BB * DD];
__device__ float s_fc[NL][BB * DD];
__device__ float s_p2[BB * NG4];
__device__ float s_p3[BB * NG4];
__device__ float s_b4[BB * NG4];
__device__ float s_pt[2][S3KC][BB][NG4];     // stage3 K-split partials
__device__ float s_pt1[S1KC][BB][512];       // stage1 K-split partials

// ---------------- bf16 split state / operands -------------------------------
__device__ __align__(16) __nv_bfloat16 g_ahh[2][NL][BB * AA];
__device__ __align__(16) __nv_bfloat16 g_ahl[2][NL][BB * AA];
__device__ __align__(16) __nv_bfloat16 g_fhh[2][NL][BB * DD];
__device__ __align__(16) __nv_bfloat16 g_fhl[2][NL][BB * DD];
__device__ __align__(16) __nv_bfloat16 g_xph[BB * DD];
__device__ __align__(16) __nv_bfloat16 g_xpl[BB * DD];
__device__ __align__(16) __nv_bfloat16 g_hph[BB * DD];
__device__ __align__(16) __nv_bfloat16 g_hpl[BB * DD];
// pre-split inputs/weights (built once per replay)
__device__ __align__(16) __nv_bfloat16 g_xh[TT * BB * DD];
__device__ __align__(16) __nv_bfloat16 g_xl[TT * BB * DD];
__device__ __align__(16) __nv_bfloat16 g_w1h[2][512 * KT1];
__device__ __align__(16) __nv_bfloat16 g_w1l[2][512 * KT1];
__device__ __align__(16) __nv_bfloat16 g_pwh[2][14336 * 128];
__device__ __align__(16) __nv_bfloat16 g_pwl[2][14336 * 128];
__device__ __align__(16) __nv_bfloat16 g_wh[2][2][NG4 * DD];
__device__ __align__(16) __nv_bfloat16 g_wl[2][2][NG4 * DD];

// ---------------- cp.async / mma helpers -------------------------------------
__device__ __forceinline__ void cp16(void* dst, const void* src) {
    unsigned d = (unsigned)__cvta_generic_to_shared(dst);
    asm volatile("cp.async.cg.shared.global [%0], [%1], 16;" :: "r"(d), "l"(src));
}
__device__ __forceinline__ void cp16w(void* dst, const void* src) {
    unsigned d = (unsigned)__cvta_generic_to_shared(dst);
    asm volatile("cp.async.ca.shared.global [%0], [%1], 16;" :: "r"(d), "l"(src));
}
__device__ __forceinline__ void cp_commit() {
    asm volatile("cp.async.commit_group;" ::: "memory");
}
__device__ __forceinline__ void cp_wait0() {
    asm volatile("cp.async.wait_group 0;" ::: "memory");
}
__device__ __forceinline__ void cp_wait1() {
    asm volatile("cp.async.wait_group 1;" ::: "memory");
}
__device__ __forceinline__ void ldsm4(unsigned r[4], unsigned addr) {
    asm volatile("ldmatrix.sync.aligned.m8n8.x4.shared.b16 {%0,%1,%2,%3}, [%4];"
                 : "=r"(r[0]), "=r"(r[1]), "=r"(r[2]), "=r"(r[3]) : "r"(addr));
}
__device__ __forceinline__ void mma16816(float d[4], const unsigned a[4],
                                         unsigned b0, unsigned b1) {
    asm volatile(
        "mma.sync.aligned.m16n8k16.row.col.f32.bf16.bf16.f32 "
        "{%0,%1,%2,%3},{%4,%5,%6,%7},{%8,%9},{%0,%1,%2,%3};"
        : "+f"(d[0]), "+f"(d[1]), "+f"(d[2]), "+f"(d[3])
        : "r"(a[0]), "r"(a[1]), "r"(a[2]), "r"(a[3]), "r"(b0), "r"(b1));
}
__device__ __forceinline__ void mma_x3(float d[4], const unsigned ah[4],
                                       const unsigned al[4],
                                       unsigned bh0, unsigned bh1,
                                       unsigned bl0, unsigned bl1) {
    mma16816(d, ah, bh0, bh1);
    mma16816(d, ah, bl0, bl1);
    mma16816(d, al, bh0, bh1);
}

// ---------------- fence-free release/acquire grid barrier --------------------
__device__ unsigned g_cnt2;
__device__ unsigned g_gen2;

__device__ __forceinline__ void grid_sync(unsigned& gen) {
    __syncthreads();
    if (threadIdx.x == 0) {
        unsigned old;
        asm volatile("atom.add.acq_rel.gpu.global.u32 %0, [%1], 1;"
                     : "=r"(old) : "l"(&g_cnt2) : "memory");
        unsigned target = gen + 1;
        if ((old & (NCTA - 1u)) == NCTA - 1u) {
            asm volatile("st.release.gpu.global.u32 [%0], %1;"
                         :: "l"(&g_gen2), "r"(target) : "memory");
        } else {
            unsigned v;
            do {
                __nanosleep(32);
                asm volatile("ld.acquire.gpu.global.u32 %0, [%1];"
                             : "=r"(v) : "l"(&g_gen2) : "memory");
            } while ((int)(v - target) < 0);
        }
    }
    gen += 1;
    __syncthreads();
}

__device__ __forceinline__ float sigf(float x) { return 1.0f / (1.0f + expf(-x)); }
__device__ __forceinline__ void bsplit(float v, __nv_bfloat16* ph, __nv_bfloat16* pl) {
    __nv_bfloat16 h = __float2bfloat16(v);
    *ph = h;
    *pl = __float2bfloat16(v - __bfloat162float(h));
}

struct Params {
    const float* x;
    const float* awih[2]; const float* awhh[2];
    const float* abih[2]; const float* abhh[2];
    const float* pw[2];   const float* pb[2];
    const float* fwih[2]; const float* fwhh[2]; const float* fb[2];
    float* out;
};

// ============================ stage 1 GEMM (tensor) ==========================
// 128 CTAs = 8 n-tiles(64 cols) x 16 k-splits(144). 16 warps = 4wm x 4wn (16x16).
// smem/buffer (halves): A_hi[64][56]@0, A_lo@3584, W_hi[64][56]@7168, W_lo@10752.
__device__ __forceinline__ void s1_fillA(
    int ch, __nv_bfloat16* buf, int kc,
    const __nv_bfloat16* __restrict__ xh, const __nv_bfloat16* __restrict__ xl,
    const __nv_bfloat16* __restrict__ fhh, const __nv_bfloat16* __restrict__ fhl,
    const __nv_bfloat16* __restrict__ aoh, const __nv_bfloat16* __restrict__ aol,
    const __nv_bfloat16* __restrict__ ash, const __nv_bfloat16* __restrict__ asl)
{
    const int k0 = kc * 144 + ch * 48;
    for (int idx = threadIdx.x; idx < 768; idx += NTHR) {
        int part = idx >= 384 ? 1 : 0;
        int rem = idx - part * 384;
        int m = rem / 6, u = rem - m * 6;
        int k = k0 + u * 8;
        const __nv_bfloat16* s;
        if (k < DD)            s = (part ? xl : xh) + m * DD + k;
        else if (k < 2 * DD)   s = (part ? fhl : fhh) + m * DD + (k - DD);
        else if (k < AIN)      s = (part ? aol : aoh) + m * AA + (k - 2 * DD);
        else                   s = (part ? asl : ash) + m * AA + (k - AIN);
        cp16(buf + part * 3584 + m * 56 + u * 8, s);
    }
}

__device__ __forceinline__ void s1_fillW(
    int ch, __nv_bfloat16* buf, int kc, int n0,
    const __nv_bfloat16* __restrict__ wh, const __nv_bfloat16* __restrict__ wl)
{
    const int k0 = kc * 144 + ch * 48;
    for (int idx = threadIdx.x; idx < 768; idx += NTHR) {
        int part = idx >= 384 ? 1 : 0;
        int rem = idx - part * 384;
        int n = rem / 6, u = rem - n * 6;
        cp16w(buf + 7168 + part * 3584 + n * 56 + u * 8,
              (part ? wl : wh) + (size_t)(n0 + n) * KT1 + k0 + u * 8);
    }
}

__device__ __forceinline__ void s1_prefetchW(int l, __nv_bfloat16* sm)
{
    const int b = blockIdx.x;
    const int nt = b >> 4, kc = b & 15;
    s1_fillW(0, sm, kc, nt * 64, g_w1h[l], g_w1l[l]);
    cp_commit();
}

__device__ __forceinline__ void stage1_gemm(
    int l, int p, __nv_bfloat16* sm,
    const __nv_bfloat16* xh, const __nv_bfloat16* xl)
{
    const int tid = threadIdx.x, b = blockIdx.x;
    const int nt = b >> 4, kc = b & 15;
    const int n0 = nt * 64;

    const __nv_bfloat16* fhh = g_fhh[p][l];
    const __nv_bfloat16* fhl = g_fhl[p][l];
    const __nv_bfloat16* aoh = (l == 0) ? g_ahh[p][1] : g_ahh[p ^ 1][0];
    const __nv_bfloat16* aol = (l == 0) ? g_ahl[p][1] : g_ahl[p ^ 1][0];
    const __nv_bfloat16* ash = g_ahh[p][l];
    const __nv_bfloat16* asl = g_ahl[p][l];
    const __nv_bfloat16* wh = g_w1h[l];
    const __nv_bfloat16* wl = g_w1l[l];

    const int w = tid >> 5, lane = tid & 31;
    const int wm = w & 3, wn = w >> 2;            // 4m x 4n groups (16x16)
    const int g = lane >> 2, t4 = lane & 3;
    const int tA = lane >> 3;
    const int arow = (tA & 1) * 8 + (lane & 7), acol = (tA >> 1) * 8;
    const int brow = (lane >> 4) * 8 + (lane & 7), bcol = ((lane >> 3) & 1) * 8;
    const unsigned base0 = (unsigned)__cvta_generic_to_shared(sm);

    float D[2][4];
    #pragma unroll
    for (int q = 0; q < 2; q++)
        D[q][0] = D[q][1] = D[q][2] = D[q][3] = 0.f;

    s1_fillA(0, sm, kc, xh, xl, fhh, fhl, aoh, aol, ash, asl);
    cp_commit();

    for (int ch = 0; ch < 3; ch++) {
        if (ch < 2) {
            __nv_bfloat16* nb = sm + ((ch + 1) & 1) * 14336;
            s1_fillA(ch + 1, nb, kc, xh, xl, fhh, fhl, aoh, aol, ash, asl);
            s1_fillW(ch + 1, nb, kc, n0, wh, wl);
            cp_commit();
            cp_wait1();
        } else {
            cp_wait0();
        }
        __syncthreads();
        const unsigned bufB = base0 + (unsigned)((ch & 1) * 14336 * 2);
        #pragma unroll
        for (int ck = 0; ck < 3; ck++) {
            const int kadd = ck * 16;
            unsigned ah[4], al[4];
            {
                unsigned a = bufB + 2u * ((wm * 16 + arow) * 56 + kadd + acol);
                ldsm4(ah, a);
                ldsm4(al, a + 2u * 3584);
            }
            unsigned bh[4], bl[4];
            {
                unsigned a = bufB + 2u * (7168 + (wn * 16 + brow) * 56 + kadd + bcol);
                ldsm4(bh, a);
                ldsm4(bl, a + 2u * 3584);
            }
            #pragma unroll
            for (int q = 0; q < 2; q++)
                mma_x3(D[q], ah, al,
                       bh[q * 2], bh[q * 2 + 1], bl[q * 2], bl[q * 2 + 1]);
        }
        __syncthreads();
    }

    int m0 = wm * 16 + g;
    #pragma unroll
    for (int q = 0; q < 2; q++) {
        int col = n0 + wn * 16 + q * 8 + 2 * t4;
        *(float2*)&s_pt1[kc][m0][col]     = make_float2(D[q][0], D[q][1]);
        *(float2*)&s_pt1[kc][m0 + 8][col] = make_float2(D[q][2], D[q][3]);
    }
}

// ============================ stage 1 pointwise ==============================
// 16 CTAs x 512: one thread per (m, j) cell; reduces 16 partials x 4 gates.
__device__ __forceinline__ void s1_point(
    int l, int p,
    const float* __restrict__ abih, const float* __restrict__ abhh)
{
    const int b = blockIdx.x;
    if (b >= 16) return;
    const int idx = b * NTHR + threadIdx.x;
    const int m = idx >> 7, j = idx & 127;

    float gt[4];
    #pragma unroll
    for (int c = 0; c < 4; c++) {
        int n = c * AA + j;
        float s = 0.f;
        #pragma unroll
        for (int kc = 0; kc < S1KC; kc++) s += __ldcg(&s_pt1[kc][m][n]);
        gt[c] = s + abih[n] + abhh[n];
    }
    float cO = __ldcg(&s_ac[l][m * AA + j]);
    float cN = sigf(gt[1]) * cO + sigf(gt[0]) * tanhf(gt[2]);
    float h  = sigf(gt[3]) * tanhf(cN);
    s_ac[l][m * AA + j] = cN;
    bsplit(h, &g_ahh[p ^ 1][l][m * AA + j], &g_ahl[p ^ 1][l][m * AA + j]);
}

// ============================ stage 2 (tensor) ===============================
// 128 CTAs x 112 n cols. K=128 one pass. 14 active warps = 2wm x 7wn.
// smem halves: A_hi[64][136]@0, A_lo@8704, W_hi[112][136]@17408, W_lo@32640.
__device__ __forceinline__ void s2_prefetchW(int l, __nv_bfloat16* sm)
{
    const int b = blockIdx.x;
    const int n0 = b * 112;
    const __nv_bfloat16* pwh = g_pwh[l];
    const __nv_bfloat16* pwl = g_pwl[l];
    for (int idx = threadIdx.x; idx < 3584; idx += NTHR) {
        int part = idx >= 1792 ? 1 : 0;
        int rem = idx - part * 1792;
        int n = rem >> 4, u = rem & 15;
        cp16w(sm + 17408 + part * 15232 + n * 136 + u * 8,
              (part ? pwl : pwh) + (size_t)(n0 + n) * 128 + u * 8);
    }
    cp_commit();
}

__device__ __forceinline__ void s2_store(
    int m, int col, float v,
    const float* __restrict__ xc, const float* __restrict__ fhOld,
    const float* __restrict__ fb)
{
    int seg = col >> 10;
    if (seg == 0) {
        float xv = v * __ldcg(xc + m * DD + col);
        bsplit(xv, &g_xph[m * DD + col], &g_xpl[m * DD + col]);
    } else if (seg == 1) {
        int cc = col - DD;
        float hv = v * __ldcg(fhOld + m * DD + cc);
        bsplit(hv, &g_hph[m * DD + cc], &g_hpl[m * DD + cc]);
    } else if (seg < 6)
        s_p2[m * NG4 + (col - 2 * DD)] = v;
    else if (seg < 10)
        s_p3[m * NG4 + (col - 6 * DD)] = v;
    else
        s_b4[m * NG4 + (col - 10 * DD)] = v * fb[col - 10 * DD];
}

__device__ __forceinline__ void stage2(
    int l, int p, const float* __restrict__ xc,
    const float* __restrict__ pb, const float* __restrict__ fb,
    __nv_bfloat16* sm)
{
    const int tid = threadIdx.x, b = blockIdx.x;
    const int n0 = b * 112;
    const float* fhOld = s_fh[p][l];
    const __nv_bfloat16* ahh = g_ahh[p ^ 1][l];
    const __nv_bfloat16* ahl = g_ahl[p ^ 1][l];

    for (int idx = tid; idx < 2048; idx += NTHR) {   // A fill
        int part = idx >> 10, rem = idx & 1023;
        int m = rem >> 4, u = rem & 15;
        cp16(sm + part * 8704 + m * 136 + u * 8,
             (part ? ahl : ahh) + m * 128 + u * 8);
    }
    cp_commit();

    const int w = tid >> 5, lane = tid & 31;
    const int wm = w & 1, wn = w >> 1;               // wn 0..7; active wn<7
    const int g = lane >> 2, t4 = lane & 3;
    const int tA = lane >> 3;
    const int arow = (tA & 1) * 8 + (lane & 7), acol = (tA >> 1) * 8;
    const int brow = (lane >> 4) * 8 + (lane & 7), bcol = ((lane >> 3) & 1) * 8;
    const unsigned base0 = (unsigned)__cvta_generic_to_shared(sm);

    float D[2][2][4];
    #pragma unroll
    for (int im = 0; im < 2; im++)
        #pragma unroll
        for (int q = 0; q < 2; q++)
            D[im][q][0] = D[im][q][1] = D[im][q][2] = D[im][q][3] = 0.f;

    cp_wait0();
    __syncthreads();

    if (wn < 7) {
        #pragma unroll
        for (int k16 = 0; k16 < 8; k16++) {
            const int kadd = k16 * 16;
            unsigned ah[2][4], al[2][4];
            #pragma unroll
            for (int im = 0; im < 2; im++) {
                unsigned a = base0 + 2u * ((wm * 32 + im * 16 + arow) * 136 + kadd + acol);
                ldsm4(ah[im], a);
                ldsm4(al[im], a + 2u * 8704);
            }
            unsigned bh[4], bl[4];
            {
                unsigned a = base0 + 2u * (17408 + (wn * 16 + brow) * 136 + kadd + bcol);
                ldsm4(bh, a);
                ldsm4(bl, a + 2u * 15232);
            }
            #pragma unroll
            for (int im = 0; im < 2; im++)
                #pragma unroll
                for (int q = 0; q < 2; q++)
                    mma_x3(D[im][q], ah[im], al[im],
                           bh[q * 2], bh[q * 2 + 1], bl[q * 2], bl[q * 2 + 1]);
        }

        #pragma unroll
        for (int im = 0; im < 2; im++) {
            int m0 = wm * 32 + im * 16 + g;
            #pragma unroll
            for (int q = 0; q < 2; q++) {
                int col = n0 + wn * 16 + q * 8 + 2 * t4;
                s2_store(m0, col,     D[im][q][0] + pb[col],     xc, fhOld, fb);
                s2_store(m0, col + 1, D[im][q][1] + pb[col + 1], xc, fhOld, fb);
                s2_store(m0 + 8, col,     D[im][q][2] + pb[col],     xc, fhOld, fb);
                s2_store(m0 + 8, col + 1, D[im][q][3] + pb[col + 1], xc, fhOld, fb);
            }
        }
    }
    __syncthreads();
}

// ============================ stage 3 GEMM (tensor) ==========================
// 128 CTAs = 2 ph x 32 nt(128 n) x 2 kc(512 k). 16 warps = 2wm x 8wn (32m x 16n).
// smem/buffer (halves): A_hi[64][40]@0, A_lo@2560, W_hi[128][40]@5120, W_lo@10240.
__device__ __forceinline__ void s3_fillA(
    int s, __nv_bfloat16* buf, int kb,
    const __nv_bfloat16* __restrict__ Ah, const __nv_bfloat16* __restrict__ Al)
{
    const int k0 = kb + s * 32;
    for (int idx = threadIdx.x; idx < 512; idx += NTHR) {
        int part = idx >> 8, m = (idx >> 2) & 63, u = idx & 3;
        cp16(buf + part * 2560 + m * 40 + u * 8,
             (part ? Al : Ah) + m * DD + k0 + u * 8);
    }
}

__device__ __forceinline__ void s3_fillW(
    int s, __nv_bfloat16* buf, int kb, int n0,
    const __nv_bfloat16* __restrict__ Wh, const __nv_bfloat16* __restrict__ Wl)
{
    const int k0 = kb + s * 32;
    for (int idx = threadIdx.x; idx < 1024; idx += NTHR) {
        int part = idx >> 9, n = (idx >> 2) & 127, u = idx & 3;
        cp16w(buf + 5120 + part * 5120 + n * 40 + u * 8,
              (part ? Wl : Wh) + (size_t)(n0 + n) * DD + k0 + u * 8);
    }
}

__device__ __forceinline__ void s3_prefetchW(int l, __nv_bfloat16* sm)
{
    const int b = blockIdx.x;
    const int ph = b >> 6, nt = (b >> 1) & 31, kc = b & 1;
    s3_fillW(0, sm, kc * 512, nt * 128, g_wh[l][ph], g_wl[l][ph]);
    cp_commit();
}

__device__ __forceinline__ void stage3_gemm(int l, __nv_bfloat16* sm)
{
    const int tid = threadIdx.x, b = blockIdx.x;
    const int ph = b >> 6;
    const int nt = (b >> 1) & 31;
    const int kc = b & 1;
    const int n0 = nt * 128;
    const int kb = kc * 512;

    const __nv_bfloat16* Ah = ph ? g_hph : g_xph;
    const __nv_bfloat16* Al = ph ? g_hpl : g_xpl;
    const __nv_bfloat16* Wh = g_wh[l][ph];
    const __nv_bfloat16* Wl = g_wl[l][ph];

    const int w = tid >> 5, lane = tid & 31;
    const int wm = w & 1, wn = w >> 1;               // 2m(32) x 8n(16)
    const int g = lane >> 2, t4 = lane & 3;
    const int tA = lane >> 3;
    const int aoff = ((tA & 1) * 8 + (lane & 7)) * 40 + (tA >> 1) * 8;
    const int boff = ((lane >> 4) * 8 + (lane & 7)) * 40 + ((lane >> 3) & 1) * 8;
    const unsigned smemBase = (unsigned)__cvta_generic_to_shared(sm);

    float D[2][2][4];
    #pragma unroll
    for (int im = 0; im < 2; im++)
        #pragma unroll
        for (int q = 0; q < 2; q++)
            D[im][q][0] = D[im][q][1] = D[im][q][2] = D[im][q][3] = 0.f;

    s3_fillA(0, sm, kb, Ah, Al);
    cp_commit();

    for (int s = 0; s < 16; s++) {
        if (s < 15) {
            __nv_bfloat16* nb = sm + ((s + 1) & 1) * 15360;
            s3_fillA(s + 1, nb, kb, Ah, Al);
            s3_fillW(s + 1, nb, kb, n0, Wh, Wl);
            cp_commit();
            cp_wait1();
        } else {
            cp_wait0();
        }
        __syncthreads();
        const unsigned bufBase = smemBase + (unsigned)((s & 1) * 15360 * 2);
        #pragma unroll
        for (int ks = 0; ks < 2; ks++) {
            const unsigned kadd = ks * 16;
            unsigned ah[2][4], al[2][4];
            #pragma unroll
            for (int im = 0; im < 2; im++) {
                unsigned base = bufBase + 2u * ((wm * 32 + im * 16) * 40 + kadd + aoff);
                ldsm4(ah[im], base);
                ldsm4(al[im], base + 2u * 2560);
            }
            unsigned bh[4], bl[4];
            {
                unsigned base = bufBase + 2u * (5120 + (wn * 16) * 40 + kadd + boff);
                ldsm4(bh, base);
                ldsm4(bl, base + 2u * 5120);
            }
            #pragma unroll
            for (int im = 0; im < 2; im++)
                #pragma unroll
                for (int q = 0; q < 2; q++)
                    mma_x3(D[im][q], ah[im], al[im],
                           bh[q * 2], bh[q * 2 + 1], bl[q * 2], bl[q * 2 + 1]);
        }
        __syncthreads();
    }

    float* dst = &s_pt[ph][kc][0][0];
    #pragma unroll
    for (int im = 0; im < 2; im++) {
        int m0 = wm * 32 + im * 16 + g;
        #pragma unroll
        for (int q = 0; q < 2; q++) {
            int col = n0 + wn * 16 + q * 8 + 2 * t4;
            *(float2*)(dst + (size_t)m0 * NG4 + col) =
                make_float2(D[im][q][0], D[im][q][1]);
            *(float2*)(dst + (size_t)(m0 + 8) * NG4 + col) =
                make_float2(D[im][q][2], D[im][q][3]);
        }
    }
}

// ============================ stage 3b (pointwise) ===========================
__device__ __forceinline__ void stage3b(
    int l, int p, int t, float* __restrict__ out)
{
    const int gidx = blockIdx.x * NTHR + threadIdx.x;
    const int m = gidx >> 10, col = gidx & 1023;

    float G[4];
    #pragma unroll
    for (int g = 0; g < 4; g++) {
        size_t cg = (size_t)m * NG4 + g * DD + col;
        float ig = __ldcg(&s_pt[0][0][0][cg]) + __ldcg(&s_pt[0][1][0][cg]);
        float hg = __ldcg(&s_pt[1][0][0][cg]) + __ldcg(&s_pt[1][1][0][cg]);
        G[g] = fmaf(ig, __ldcg(&s_p2[cg]), __ldcg(&s_b4[cg]))
             + hg * __ldcg(&s_p3[cg]);
    }
    float cO = __ldcg(&s_fc[l][m * DD + col]);
    float cN = sigf(G[1]) * cO + sigf(G[0]) * tanhf(G[2]);
    float h  = sigf(G[3]) * tanhf(cN);
    s_fc[l][m * DD + col] = cN;
    s_fh[p ^ 1][l][m * DD + col] = h;
    bsplit(h, &g_fhh[p ^ 1][l][m * DD + col], &g_fhl[p ^ 1][l][m * DD + col]);
    if (l == 1) out[((size_t)t * BB + m) * DD + col] = h;
}

// ---------------- persistent kernel ----------------------------------------
__global__ void __launch_bounds__(NTHR, 1) alstm_persistent(Params P)
{
    extern __shared__ __align__(16) float smf[];
    __nv_bfloat16* sm = (__nv_bfloat16*)smf;
    const int tid = threadIdx.x, b = blockIdx.x;
    const int gtid = b * NTHR + tid, gsz = NCTA * NTHR;

    unsigned gen;
    asm volatile("ld.acquire.gpu.global.u32 %0, [%1];" : "=r"(gen) : "l"(&g_gen2));

    {   // zero recurrent state each replay
        float* z2 = &s_ac[0][0];
        for (int i = gtid; i < NL * BB * AA; i += gsz) z2[i] = 0.f;
        float* z3 = &s_fh[0][0][0];
        for (int i = gtid; i < 2 * NL * BB * DD; i += gsz) z3[i] = 0.f;
        float* z4 = &s_fc[0][0];
        for (int i = gtid; i < NL * BB * DD; i += gsz) z4[i] = 0.f;
        __nv_bfloat16* z5 = &g_ahh[0][0][0];
        __nv_bfloat16* z6 = &g_ahl[0][0][0];
        for (int i = gtid; i < 2 * NL * BB * AA; i += gsz) { z5[i] = __nv_bfloat16(0.f); z6[i] = __nv_bfloat16(0.f); }
        __nv_bfloat16* z7 = &g_fhh[0][0][0];
        __nv_bfloat16* z8 = &g_fhl[0][0][0];
        for (int i = gtid; i < 2 * NL * BB * DD; i += gsz) { z7[i] = __nv_bfloat16(0.f); z8[i] = __nv_bfloat16(0.f); }
    }
    {   // split x (whole sequence)
        const float4* s4 = (const float4*)P.x;
        for (int i = gtid; i < TT * BB * DD / 4; i += gsz) {
            float4 v = s4[i];
            float f[4] = {v.x, v.y, v.z, v.w};
            #pragma unroll
            for (int q = 0; q < 4; q++)
                bsplit(f[q], &g_xh[4 * i + q], &g_xl[4 * i + q]);
        }
    }
    {   // split stage3 weights
        const float* Wsrc[4] = {P.fwih[0], P.fwhh[0], P.fwih[1], P.fwhh[1]};
        #pragma unroll
        for (int mtx = 0; mtx < 4; mtx++) {
            const float4* s4 = (const float4*)Wsrc[mtx];
            __nv_bfloat16* dh = &g_wh[mtx >> 1][mtx & 1][0];
            __nv_bfloat16* dl = &g_wl[mtx >> 1][mtx & 1][0];
            for (int i = gtid; i < NG4 * DD / 4; i += gsz) {
                float4 v = s4[i];
                float f[4] = {v.x, v.y, v.z, v.w};
                #pragma unroll
                for (int q = 0; q < 4; q++)
                    bsplit(f[q], &dh[4 * i + q], &dl[4 * i + q]);
            }
        }
    }
    {   // split pw
        #pragma unroll
        for (int l = 0; l < 2; l++) {
            const float4* s4 = (const float4*)P.pw[l];
            for (int i = gtid; i < 14336 * 128 / 4; i += gsz) {
                float4 v = s4[i];
                float f[4] = {v.x, v.y, v.z, v.w};
                #pragma unroll
                for (int q = 0; q < 4; q++)
                    bsplit(f[q], &g_pwh[l][4 * i + q], &g_pwl[l][4 * i + q]);
            }
        }
    }
    {   // build composite stage1 weights
        #pragma unroll
        for (int l = 0; l < 2; l++) {
            const float* wih = P.awih[l];
            const float* whh = P.awhh[l];
            for (int i = gtid; i < 512 * KT1; i += gsz) {
                int n = i / KT1, k = i - n * KT1;
                float v = (k < AIN) ? wih[(size_t)n * AIN + k]
                                    : whh[n * AA + (k - AIN)];
                bsplit(v, &g_w1h[l][i], &g_w1l[l][i]);
            }
        }
    }
    grid_sync(gen);

    s1_prefetchW(0, sm);

    for (int t = 0; t < TT; t++) {
        const int p = t & 1;
        #pragma unroll
        for (int l = 0; l < NL; l++) {
            const __nv_bfloat16* xh = (l == 0) ? g_xh + (size_t)t * BB * DD
                                               : g_fhh[p ^ 1][0];
            const __nv_bfloat16* xl = (l == 0) ? g_xl + (size_t)t * BB * DD
                                               : g_fhl[p ^ 1][0];
            stage1_gemm(l, p, sm, xh, xl);
            s2_prefetchW(l, sm);                 // hides behind barrier + s1_point
            grid_sync(gen);
            s1_point(l, p, P.abih[l], P.abhh[l]);
            grid_sync(gen);
            const float* xc = (l == 0) ? P.x + (size_t)t * BB * DD
                                       : s_fh[p ^ 1][0];
            stage2(l, p, xc, P.pb[l], P.fb[l], sm);
            s3_prefetchW(l, sm);
            grid_sync(gen);
            stage3_gemm(l, sm);
            grid_sync(gen);
            s1_prefetchW(l ^ 1, sm);
            stage3b(l, p, t, P.out);
            grid_sync(gen);
        }
    }
    cp_wait0();
}

// ---------------- host launch ----------------------------------------------
extern "C" void kernel_launch(void* const* d_in, const int* in_sizes, int n_in,
                              void* d_out, int out_size)
{
    Params P;
    P.x       = (const float*)d_in[0];
    P.awih[0] = (const float*)d_in[1];  P.awih[1] = (const float*)d_in[10];
    P.awhh[0] = (const float*)d_in[2];  P.awhh[1] = (const float*)d_in[11];
    P.abih[0] = (const float*)d_in[3];  P.abih[1] = (const float*)d_in[12];
    P.abhh[0] = (const float*)d_in[4];  P.abhh[1] = (const float*)d_in[13];
    P.pw[0]   = (const float*)d_in[5];  P.pw[1]   = (const float*)d_in[14];
    P.pb[0]   = (const float*)d_in[6];  P.pb[1]   = (const float*)d_in[15];
    P.fwih[0] = (const float*)d_in[7];  P.fwih[1] = (const float*)d_in[16];
    P.fwhh[0] = (const float*)d_in[8];  P.fwhh[1] = (const float*)d_in[17];
    P.fb[0]   = (const float*)d_in[9];  P.fb[1]   = (const float*)d_in[18];
    P.out     = (float*)d_out;

    cudaFuncSetAttribute(alstm_persistent,
                         cudaFuncAttributeMaxDynamicSharedMemorySize,
                         SMEM_BYTES);
    alstm_persistent<<<NCTA, NTHR, SMEM_BYTES>>>(P);
}

// round 15
// speedup vs baseline: 1.4268x; 1.1426x over previous
#include <cuda_runtime.h>
#include <cuda_bf16.h>
#include <math.h>

#define TT    512
#define BB    64
#define DD    1024
#define AA    128
#define AIN   2176           // D + D + A
#define KT1   2304           // composite K for stage1
#define NL    2
#define NCTA  256
#define NTHR  256
#define NG4   4096           // 4 gates * D
#define S1KC  16             // stage1 K-splits (144 k each)
#define SMEM_BYTES 92160     // stage3: 3 x 15360 halves

// ---------------- fp32 persistent state -------------------------------------
__device__ float s_ac[NL][BB * AA];
__device__ float s_fh[2][NL][BB * DD];
__device__ float s_fc[NL][BB * DD];
__device__ float s_p2[BB * NG4];
__device__ float s_p3[BB * NG4];
__device__ float s_b4[BB * NG4];
__device__ float s_pt[2][4][BB][NG4];        // stage3 K-split partials
__device__ float s_pt1[S1KC][BB][512];       // stage1 K-split partials

// ---------------- bf16 split state / operands -------------------------------
__device__ __align__(16) __nv_bfloat16 g_ahh[2][NL][BB * AA];
__device__ __align__(16) __nv_bfloat16 g_ahl[2][NL][BB * AA];
__device__ __align__(16) __nv_bfloat16 g_fhh[2][NL][BB * DD];
__device__ __align__(16) __nv_bfloat16 g_fhl[2][NL][BB * DD];
__device__ __align__(16) __nv_bfloat16 g_xph[BB * DD];
__device__ __align__(16) __nv_bfloat16 g_xpl[BB * DD];
__device__ __align__(16) __nv_bfloat16 g_hph[BB * DD];
__device__ __align__(16) __nv_bfloat16 g_hpl[BB * DD];
// pre-split inputs/weights (built once per replay)
__device__ __align__(16) __nv_bfloat16 g_xh[TT * BB * DD];
__device__ __align__(16) __nv_bfloat16 g_xl[TT * BB * DD];
__device__ __align__(16) __nv_bfloat16 g_w1h[2][512 * KT1];
__device__ __align__(16) __nv_bfloat16 g_w1l[2][512 * KT1];
__device__ __align__(16) __nv_bfloat16 g_pwh[2][14336 * 128];
__device__ __align__(16) __nv_bfloat16 g_pwl[2][14336 * 128];
__device__ __align__(16) __nv_bfloat16 g_wh[2][2][NG4 * DD];
__device__ __align__(16) __nv_bfloat16 g_wl[2][2][NG4 * DD];

// ---------------- cp.async / mma helpers -------------------------------------
__device__ __forceinline__ void cp16(void* dst, const void* src) {
    unsigned d = (unsigned)__cvta_generic_to_shared(dst);
    asm volatile("cp.async.cg.shared.global [%0], [%1], 16;" :: "r"(d), "l"(src));
}
__device__ __forceinline__ void cp16w(void* dst, const void* src) {
    unsigned d = (unsigned)__cvta_generic_to_shared(dst);
    asm volatile("cp.async.ca.shared.global [%0], [%1], 16;" :: "r"(d), "l"(src));
}
__device__ __forceinline__ void cp_commit() {
    asm volatile("cp.async.commit_group;" ::: "memory");
}
__device__ __forceinline__ void cp_wait0() {
    asm volatile("cp.async.wait_group 0;" ::: "memory");
}
__device__ __forceinline__ void cp_wait1() {
    asm volatile("cp.async.wait_group 1;" ::: "memory");
}
__device__ __forceinline__ void cp_wait2() {
    asm volatile("cp.async.wait_group 2;" ::: "memory");
}
__device__ __forceinline__ void ldsm4(unsigned r[4], unsigned addr) {
    asm volatile("ldmatrix.sync.aligned.m8n8.x4.shared.b16 {%0,%1,%2,%3}, [%4];"
                 : "=r"(r[0]), "=r"(r[1]), "=r"(r[2]), "=r"(r[3]) : "r"(addr));
}
__device__ __forceinline__ void mma16816(float d[4], const unsigned a[4],
                                         unsigned b0, unsigned b1) {
    asm volatile(
        "mma.sync.aligned.m16n8k16.row.col.f32.bf16.bf16.f32 "
        "{%0,%1,%2,%3},{%4,%5,%6,%7},{%8,%9},{%0,%1,%2,%3};"
        : "+f"(d[0]), "+f"(d[1]), "+f"(d[2]), "+f"(d[3])
        : "r"(a[0]), "r"(a[1]), "r"(a[2]), "r"(a[3]), "r"(b0), "r"(b1));
}
__device__ __forceinline__ void mma_x3(float d[4], const unsigned ah[4],
                                       const unsigned al[4],
                                       unsigned bh0, unsigned bh1,
                                       unsigned bl0, unsigned bl1) {
    mma16816(d, ah, bh0, bh1);
    mma16816(d, ah, bl0, bl1);
    mma16816(d, al, bh0, bh1);
}

// ---------------- fence-free release/acquire grid barrier --------------------
__device__ unsigned g_cnt2;
__device__ unsigned g_gen2;

__device__ __forceinline__ void grid_sync(unsigned& gen) {
    __syncthreads();
    if (threadIdx.x == 0) {
        unsigned old;
        asm volatile("atom.add.acq_rel.gpu.global.u32 %0, [%1], 1;"
                     : "=r"(old) : "l"(&g_cnt2) : "memory");
        unsigned target = gen + 1;
        if ((old & (NCTA - 1u)) == NCTA - 1u) {
            asm volatile("st.release.gpu.global.u32 [%0], %1;"
                         :: "l"(&g_gen2), "r"(target) : "memory");
        } else {
            unsigned v;
            do {
                __nanosleep(32);
                asm volatile("ld.acquire.gpu.global.u32 %0, [%1];"
                             : "=r"(v) : "l"(&g_gen2) : "memory");
            } while ((int)(v - target) < 0);
        }
    }
    gen += 1;
    __syncthreads();
}

__device__ __forceinline__ float sigf(float x) { return 1.0f / (1.0f + expf(-x)); }
__device__ __forceinline__ void bsplit(float v, __nv_bfloat16* ph, __nv_bfloat16* pl) {
    __nv_bfloat16 h = __float2bfloat16(v);
    *ph = h;
    *pl = __float2bfloat16(v - __bfloat162float(h));
}

struct Params {
    const float* x;
    const float* awih[2]; const float* awhh[2];
    const float* abih[2]; const float* abhh[2];
    const float* pw[2];   const float* pb[2];
    const float* fwih[2]; const float* fwhh[2]; const float* fb[2];
    float* out;
};

// ============================ stage 1 GEMM (tensor) ==========================
// 128 CTAs = 8 n-tiles(64 cols) x 16 k-splits(144). Fully prefetched: 3 chunk
// buffers (W pre-barrier, A up-front). Buffer layout (halves): A_hi[64][56]@0,
// A_lo@3584, W_hi[64][56]@7168, W_lo@10752; buffer stride 14336.
__device__ __forceinline__ void s1_fillA(
    int ch, __nv_bfloat16* buf, int kc,
    const __nv_bfloat16* __restrict__ xh, const __nv_bfloat16* __restrict__ xl,
    const __nv_bfloat16* __restrict__ fhh, const __nv_bfloat16* __restrict__ fhl,
    const __nv_bfloat16* __restrict__ aoh, const __nv_bfloat16* __restrict__ aol,
    const __nv_bfloat16* __restrict__ ash, const __nv_bfloat16* __restrict__ asl)
{
    const int tid = threadIdx.x;
    const int k0 = kc * 144 + ch * 48;
    #pragma unroll
    for (int r = 0; r < 3; r++) {
        int idx = r * 256 + tid;
        int part = idx >= 384 ? 1 : 0;
        int rem = idx - part * 384;
        int m = rem / 6, u = rem - m * 6;
        int k = k0 + u * 8;
        const __nv_bfloat16* s;
        if (k < DD)            s = (part ? xl : xh) + m * DD + k;
        else if (k < 2 * DD)   s = (part ? fhl : fhh) + m * DD + (k - DD);
        else if (k < AIN)      s = (part ? aol : aoh) + m * AA + (k - 2 * DD);
        else                   s = (part ? asl : ash) + m * AA + (k - AIN);
        cp16(buf + part * 3584 + m * 56 + u * 8, s);
    }
}

__device__ __forceinline__ void s1_fillW(
    int ch, __nv_bfloat16* buf, int kc, int n0,
    const __nv_bfloat16* __restrict__ wh, const __nv_bfloat16* __restrict__ wl)
{
    const int tid = threadIdx.x;
    const int k0 = kc * 144 + ch * 48;
    #pragma unroll
    for (int r = 0; r < 3; r++) {
        int idx = r * 256 + tid;
        int part = idx >= 384 ? 1 : 0;
        int rem = idx - part * 384;
        int n = rem / 6, u = rem - n * 6;
        cp16w(buf + 7168 + part * 3584 + n * 56 + u * 8,
              (part ? wl : wh) + (size_t)(n0 + n) * KT1 + k0 + u * 8);
    }
}

// Prefetch W for ALL 3 chunks (one group) — issued before the preceding barrier.
__device__ __forceinline__ void s1_prefetchW(int l, __nv_bfloat16* sm)
{
    const int b = blockIdx.x;
    if (b >= 128) return;
    const int nt = b >> 4, kc = b & 15;
    #pragma unroll
    for (int ch = 0; ch < 3; ch++)
        s1_fillW(ch, sm + ch * 14336, kc, nt * 64, g_w1h[l], g_w1l[l]);
    cp_commit();
}

__device__ __forceinline__ void stage1_gemm(
    int l, int p, __nv_bfloat16* sm,
    const __nv_bfloat16* xh, const __nv_bfloat16* xl)
{
    const int tid = threadIdx.x, b = blockIdx.x;
    if (b >= 128) return;
    const int nt = b >> 4, kc = b & 15;
    const int n0 = nt * 64;

    const __nv_bfloat16* fhh = g_fhh[p][l];
    const __nv_bfloat16* fhl = g_fhl[p][l];
    const __nv_bfloat16* aoh = (l == 0) ? g_ahh[p][1] : g_ahh[p ^ 1][0];
    const __nv_bfloat16* aol = (l == 0) ? g_ahl[p][1] : g_ahl[p ^ 1][0];
    const __nv_bfloat16* ash = g_ahh[p][l];
    const __nv_bfloat16* asl = g_ahl[p][l];

    const int w = tid >> 5, lane = tid & 31;
    const int wm = w & 1, wn = w >> 1;
    const int g = lane >> 2, t4 = lane & 3;
    const int tA = lane >> 3;
    const int arow = (tA & 1) * 8 + (lane & 7), acol = (tA >> 1) * 8;
    const int brow = (lane >> 4) * 8 + (lane & 7), bcol = ((lane >> 3) & 1) * 8;
    const unsigned base0 = (unsigned)__cvta_generic_to_shared(sm);

    float D[2][2][4];
    #pragma unroll
    for (int im = 0; im < 2; im++)
        #pragma unroll
        for (int q = 0; q < 2; q++)
            D[im][q][0] = D[im][q][1] = D[im][q][2] = D[im][q][3] = 0.f;

    // All A fills up-front (W group already outstanding from pre-barrier).
    s1_fillA(0, sm,          kc, xh, xl, fhh, fhl, aoh, aol, ash, asl);
    cp_commit();
    s1_fillA(1, sm + 14336,  kc, xh, xl, fhh, fhl, aoh, aol, ash, asl);
    cp_commit();
    s1_fillA(2, sm + 28672,  kc, xh, xl, fhh, fhl, aoh, aol, ash, asl);
    cp_commit();

    #pragma unroll
    for (int ch = 0; ch < 3; ch++) {
        if (ch == 0) cp_wait2();
        else if (ch == 1) cp_wait1();
        else cp_wait0();
        __syncthreads();
        const unsigned bufB = base0 + (unsigned)(ch * 14336 * 2);
        #pragma unroll
        for (int ck = 0; ck < 3; ck++) {
            const int kadd = ck * 16;
            unsigned ah[2][4], al[2][4];
            #pragma unroll
            for (int im = 0; im < 2; im++) {
                unsigned a = bufB + 2u * ((wm * 32 + im * 16 + arow) * 56 + kadd + acol);
                ldsm4(ah[im], a);
                ldsm4(al[im], a + 2u * 3584);
            }
            unsigned bh[4], bl[4];
            {
                unsigned a = bufB + 2u * (7168 + (wn * 16 + brow) * 56 + kadd + bcol);
                ldsm4(bh, a);
                ldsm4(bl, a + 2u * 3584);
            }
            #pragma unroll
            for (int im = 0; im < 2; im++)
                #pragma unroll
                for (int q = 0; q < 2; q++)
                    mma_x3(D[im][q], ah[im], al[im],
                           bh[q * 2], bh[q * 2 + 1], bl[q * 2], bl[q * 2 + 1]);
        }
        __syncthreads();
    }

    #pragma unroll
    for (int im = 0; im < 2; im++) {
        int m0 = wm * 32 + im * 16 + g;
        #pragma unroll
        for (int q = 0; q < 2; q++) {
            int col = n0 + wn * 16 + q * 8 + 2 * t4;
            *(float2*)&s_pt1[kc][m0][col]     = make_float2(D[im][q][0], D[im][q][1]);
            *(float2*)&s_pt1[kc][m0 + 8][col] = make_float2(D[im][q][2], D[im][q][3]);
        }
    }
}

// ============================ stage 1 pointwise ==============================
// 32 CTAs x 256: one thread per (m, j) cell; reduces 16 partials x 4 gates.
__device__ __forceinline__ void s1_point(
    int l, int p,
    const float* __restrict__ abih, const float* __restrict__ abhh)
{
    const int b = blockIdx.x;
    if (b >= 32) return;
    const int idx = b * 256 + threadIdx.x;
    const int m = idx >> 7, j = idx & 127;

    float gt[4];
    #pragma unroll
    for (int c = 0; c < 4; c++) {
        int n = c * AA + j;
        float s = 0.f;
        #pragma unroll
        for (int kc = 0; kc < S1KC; kc++) s += __ldcg(&s_pt1[kc][m][n]);
        gt[c] = s + abih[n] + abhh[n];
    }
    float cO = __ldcg(&s_ac[l][m * AA + j]);
    float cN = sigf(gt[1]) * cO + sigf(gt[0]) * tanhf(gt[2]);
    float h  = sigf(gt[3]) * tanhf(cN);
    s_ac[l][m * AA + j] = cN;
    bsplit(h, &g_ahh[p ^ 1][l][m * AA + j], &g_ahl[p ^ 1][l][m * AA + j]);
}

// ============================ stage 2 (tensor) ===============================
// 224 CTAs x 64 n. smem halves: A_hi[64][136]@0, A_lo@8704, W_hi@17408, W_lo@26112.
__device__ __forceinline__ void s2_prefetchW(int l, __nv_bfloat16* sm)
{
    const int tid = threadIdx.x, b = blockIdx.x;
    if (b >= 224) return;
    const int n0 = b * 64;
    const __nv_bfloat16* pwh = g_pwh[l];
    const __nv_bfloat16* pwl = g_pwl[l];
    #pragma unroll
    for (int r = 0; r < 8; r++) {
        int idx = r * 256 + tid;
        int part = idx >> 10, rem = idx & 1023;
        int n = rem >> 4, u = rem & 15;
        cp16w(sm + 17408 + part * 8704 + n * 136 + u * 8,
              (part ? pwl : pwh) + (size_t)(n0 + n) * 128 + u * 8);
    }
    cp_commit();
}

__device__ __forceinline__ void s2_store(
    int seg, int m, int col, float v,
    const float* __restrict__ xc, const float* __restrict__ fhOld,
    const float* __restrict__ fb)
{
    if (seg == 0) {
        float xv = v * __ldcg(xc + m * DD + col);
        bsplit(xv, &g_xph[m * DD + col], &g_xpl[m * DD + col]);
    } else if (seg == 1) {
        int cc = col - DD;
        float hv = v * __ldcg(fhOld + m * DD + cc);
        bsplit(hv, &g_hph[m * DD + cc], &g_hpl[m * DD + cc]);
    } else if (seg < 6)
        s_p2[m * NG4 + (col - 2 * DD)] = v;
    else if (seg < 10)
        s_p3[m * NG4 + (col - 6 * DD)] = v;
    else
        s_b4[m * NG4 + (col - 10 * DD)] = v * fb[col - 10 * DD];
}

__device__ __forceinline__ void stage2(
    int l, int p, const float* __restrict__ xc,
    const float* __restrict__ pb, const float* __restrict__ fb,
    __nv_bfloat16* sm)
{
    const int tid = threadIdx.x, b = blockIdx.x;
    if (b >= 224) return;
    const int n0 = b * 64;
    const float* fhOld = s_fh[p][l];
    const __nv_bfloat16* ahh = g_ahh[p ^ 1][l];
    const __nv_bfloat16* ahl = g_ahl[p ^ 1][l];

    #pragma unroll
    for (int r = 0; r < 8; r++) {            // A fill (W prefetched earlier)
        int idx = r * 256 + tid;
        int part = idx >> 10, rem = idx & 1023;
        int m = rem >> 4, u = rem & 15;
        cp16(sm + part * 8704 + m * 136 + u * 8,
             (part ? ahl : ahh) + m * 128 + u * 8);
    }
    cp_commit();

    const int w = tid >> 5, lane = tid & 31;
    const int wm = w & 1, wn = w >> 1;
    const int g = lane >> 2, t4 = lane & 3;
    const int tA = lane >> 3;
    const int arow = (tA & 1) * 8 + (lane & 7), acol = (tA >> 1) * 8;
    const int brow = (lane >> 4) * 8 + (lane & 7), bcol = ((lane >> 3) & 1) * 8;
    const unsigned base0 = (unsigned)__cvta_generic_to_shared(sm);

    float D[2][2][4];
    #pragma unroll
    for (int im = 0; im < 2; im++)
        #pragma unroll
        for (int q = 0; q < 2; q++)
            D[im][q][0] = D[im][q][1] = D[im][q][2] = D[im][q][3] = 0.f;

    cp_wait0();
    __syncthreads();

    #pragma unroll
    for (int k16 = 0; k16 < 8; k16++) {
        const int kadd = k16 * 16;
        unsigned ah[2][4], al[2][4];
        #pragma unroll
        for (int im = 0; im < 2; im++) {
            unsigned a = base0 + 2u * ((wm * 32 + im * 16 + arow) * 136 + kadd + acol);
            ldsm4(ah[im], a);
            ldsm4(al[im], a + 2u * 8704);
        }
        unsigned bh[4], bl[4];
        {
            unsigned a = base0 + 2u * (17408 + (wn * 16 + brow) * 136 + kadd + bcol);
            ldsm4(bh, a);
            ldsm4(bl, a + 2u * 8704);
        }
        #pragma unroll
        for (int im = 0; im < 2; im++)
            #pragma unroll
            for (int q = 0; q < 2; q++)
                mma_x3(D[im][q], ah[im], al[im],
                       bh[q * 2], bh[q * 2 + 1], bl[q * 2], bl[q * 2 + 1]);
    }
    __syncthreads();

    const int seg = n0 >> 10;
    #pragma unroll
    for (int im = 0; im < 2; im++) {
        int m0 = wm * 32 + im * 16 + g;
        #pragma unroll
        for (int q = 0; q < 2; q++) {
            int col = n0 + wn * 16 + q * 8 + 2 * t4;
            s2_store(seg, m0, col,     D[im][q][0] + pb[col],     xc, fhOld, fb);
            s2_store(seg, m0, col + 1, D[im][q][1] + pb[col + 1], xc, fhOld, fb);
            s2_store(seg, m0 + 8, col,     D[im][q][2] + pb[col],     xc, fhOld, fb);
            s2_store(seg, m0 + 8, col + 1, D[im][q][3] + pb[col + 1], xc, fhOld, fb);
        }
    }
}

// ============================ stage 3 GEMM (tensor, 3-deep pipeline) =========
// 256 CTAs = 2 ph x 32 nt(128 n) x 4 kc(256 k). 8 chunks of 32 k, 3 buffers.
// Buffer layout (halves): A_hi[64][40]@0, A_lo@2560, W_hi[128][40]@5120,
// W_lo@10240; buffer stride 15360.
__device__ __forceinline__ void s3_fillA(
    int s, __nv_bfloat16* buf, int kb,
    const __nv_bfloat16* __restrict__ Ah, const __nv_bfloat16* __restrict__ Al)
{
    const int tid = threadIdx.x;
    const int k0 = kb + s * 32;
    #pragma unroll
    for (int r = 0; r < 2; r++) {
        int idx = r * 256 + tid;
        int part = idx >> 8, m = (idx >> 2) & 63, u = idx & 3;
        cp16(buf + part * 2560 + m * 40 + u * 8,
             (part ? Al : Ah) + m * DD + k0 + u * 8);
    }
}

__device__ __forceinline__ void s3_fillW(
    int s, __nv_bfloat16* buf, int kb, int n0,
    const __nv_bfloat16* __restrict__ Wh, const __nv_bfloat16* __restrict__ Wl)
{
    const int tid = threadIdx.x;
    const int k0 = kb + s * 32;
    #pragma unroll
    for (int r = 0; r < 4; r++) {
        int idx = r * 256 + tid;
        int part = idx >> 9, n = (idx >> 2) & 127, u = idx & 3;
        cp16w(buf + 5120 + part * 5120 + n * 40 + u * 8,
              (part ? Wl : Wh) + (size_t)(n0 + n) * DD + k0 + u * 8);
    }
}

__device__ __forceinline__ void s3_prefetchW(int l, __nv_bfloat16* sm)
{
    const int b = blockIdx.x;
    const int ph = b >> 7, nt = (b & 127) >> 2, kc = b & 3;
    s3_fillW(0, sm, kc * 256, nt * 128, g_wh[l][ph], g_wl[l][ph]);
    cp_commit();
}

__device__ __forceinline__ void stage3_gemm(int l, __nv_bfloat16* sm)
{
    const int tid = threadIdx.x, b = blockIdx.x;
    const int ph = b >> 7;
    const int nt = (b & 127) >> 2;
    const int kc = b & 3;
    const int n0 = nt * 128;
    const int kb = kc * 256;

    const __nv_bfloat16* Ah = ph ? g_hph : g_xph;
    const __nv_bfloat16* Al = ph ? g_hpl : g_xpl;
    const __nv_bfloat16* Wh = g_wh[l][ph];
    const __nv_bfloat16* Wl = g_wl[l][ph];

    const int w = tid >> 5, lane = tid & 31;
    const int wm = w & 1, wn = w >> 1;
    const int g = lane >> 2, t4 = lane & 3;
    const int tA = lane >> 3;
    const int aoff = ((tA & 1) * 8 + (lane & 7)) * 40 + (tA >> 1) * 8;
    const int boff = ((lane >> 4) * 8 + (lane & 7)) * 40 + ((lane >> 3) & 1) * 8;
    const unsigned smemBase = (unsigned)__cvta_generic_to_shared(sm);

    float D[2][4][4];
    #pragma unroll
    for (int im = 0; im < 2; im++)
        #pragma unroll
        for (int q = 0; q < 4; q++)
            D[im][q][0] = D[im][q][1] = D[im][q][2] = D[im][q][3] = 0.f;

    // Pipeline prologue: chunk0 (W pre-barrier) A-fill, chunk1 full fill.
    s3_fillA(0, sm, kb, Ah, Al);
    cp_commit();
    {
        __nv_bfloat16* nb = sm + 15360;
        s3_fillA(1, nb, kb, Ah, Al);
        s3_fillW(1, nb, kb, n0, Wh, Wl);
        cp_commit();
    }

    for (int s = 0; s < 8; s++) {
        if (s < 6) {
            __nv_bfloat16* nb = sm + ((s + 2) % 3) * 15360;
            s3_fillA(s + 2, nb, kb, Ah, Al);
            s3_fillW(s + 2, nb, kb, n0, Wh, Wl);
            cp_commit();
            cp_wait2();
        } else if (s == 6) {
            cp_wait1();
        } else {
            cp_wait0();
        }
        __syncthreads();
        const unsigned bufBase = smemBase + (unsigned)((s % 3) * 15360 * 2);
        #pragma unroll
        for (int ks = 0; ks < 2; ks++) {
            const unsigned kadd = ks * 16;
            unsigned ah[2][4], al[2][4];
            #pragma unroll
            for (int im = 0; im < 2; im++) {
                unsigned base = bufBase + 2u * ((wm * 32 + im * 16) * 40 + kadd + aoff);
                ldsm4(ah[im], base);
                ldsm4(al[im], base + 2u * 2560);
            }
            unsigned bh[2][4], bl[2][4];
            #pragma unroll
            for (int in2 = 0; in2 < 2; in2++) {
                unsigned base = bufBase + 2u * (5120 + (wn * 32 + in2 * 16) * 40 + kadd + boff);
                ldsm4(bh[in2], base);
                ldsm4(bl[in2], base + 2u * 5120);
            }
            #pragma unroll
            for (int im = 0; im < 2; im++)
                #pragma unroll
                for (int in8 = 0; in8 < 4; in8++) {
                    int in2 = in8 >> 1, o = (in8 & 1) * 2;
                    mma_x3(D[im][in8], ah[im], al[im],
                           bh[in2][o], bh[in2][o + 1], bl[in2][o], bl[in2][o + 1]);
                }
        }
        __syncthreads();
    }

    float* dst = &s_pt[ph][kc][0][0];
    #pragma unroll
    for (int im = 0; im < 2; im++) {
        int m0 = wm * 32 + im * 16 + g;
        #pragma unroll
        for (int in8 = 0; in8 < 4; in8++) {
            int col = n0 + wn * 32 + in8 * 8 + 2 * t4;
            *(float2*)(dst + (size_t)m0 * NG4 + col) =
                make_float2(D[im][in8][0], D[im][in8][1]);
            *(float2*)(dst + (size_t)(m0 + 8) * NG4 + col) =
                make_float2(D[im][in8][2], D[im][in8][3]);
        }
    }
}

// ============================ stage 3b (pointwise) ===========================
__device__ __forceinline__ void stage3b(
    int l, int p, int t, float* __restrict__ out)
{
    const int gidx = blockIdx.x * NTHR + threadIdx.x;
    const int m = gidx >> 10, col = gidx & 1023;

    float G[4];
    #pragma unroll
    for (int g = 0; g < 4; g++) {
        size_t cg = (size_t)m * NG4 + g * DD + col;
        float ig = __ldcg(&s_pt[0][0][0][cg]) + __ldcg(&s_pt[0][1][0][cg])
                 + __ldcg(&s_pt[0][2][0][cg]) + __ldcg(&s_pt[0][3][0][cg]);
        float hg = __ldcg(&s_pt[1][0][0][cg]) + __ldcg(&s_pt[1][1][0][cg])
                 + __ldcg(&s_pt[1][2][0][cg]) + __ldcg(&s_pt[1][3][0][cg]);
        G[g] = fmaf(ig, __ldcg(&s_p2[cg]), __ldcg(&s_b4[cg]))
             + hg * __ldcg(&s_p3[cg]);
    }
    float cO = __ldcg(&s_fc[l][m * DD + col]);
    float cN = sigf(G[1]) * cO + sigf(G[0]) * tanhf(G[2]);
    float h  = sigf(G[3]) * tanhf(cN);
    s_fc[l][m * DD + col] = cN;
    s_fh[p ^ 1][l][m * DD + col] = h;
    bsplit(h, &g_fhh[p ^ 1][l][m * DD + col], &g_fhl[p ^ 1][l][m * DD + col]);
    if (l == 1) out[((size_t)t * BB + m) * DD + col] = h;
}

// ---------------- persistent kernel ----------------------------------------
__global__ void __launch_bounds__(NTHR, 2) alstm_persistent(Params P)
{
    extern __shared__ __align__(16) float smf[];
    __nv_bfloat16* sm = (__nv_bfloat16*)smf;
    const int tid = threadIdx.x, b = blockIdx.x;
    const int gtid = b * NTHR + tid, gsz = NCTA * NTHR;

    unsigned gen;
    asm volatile("ld.acquire.gpu.global.u32 %0, [%1];" : "=r"(gen) : "l"(&g_gen2));

    {   // zero recurrent state each replay
        float* z2 = &s_ac[0][0];
        for (int i = gtid; i < NL * BB * AA; i += gsz) z2[i] = 0.f;
        float* z3 = &s_fh[0][0][0];
        for (int i = gtid; i < 2 * NL * BB * DD; i += gsz) z3[i] = 0.f;
        float* z4 = &s_fc[0][0];
        for (int i = gtid; i < NL * BB * DD; i += gsz) z4[i] = 0.f;
        __nv_bfloat16* z5 = &g_ahh[0][0][0];
        __nv_bfloat16* z6 = &g_ahl[0][0][0];
        for (int i = gtid; i < 2 * NL * BB * AA; i += gsz) { z5[i] = __nv_bfloat16(0.f); z6[i] = __nv_bfloat16(0.f); }
        __nv_bfloat16* z7 = &g_fhh[0][0][0];
        __nv_bfloat16* z8 = &g_fhl[0][0][0];
        for (int i = gtid; i < 2 * NL * BB * DD; i += gsz) { z7[i] = __nv_bfloat16(0.f); z8[i] = __nv_bfloat16(0.f); }
    }
    {   // split x (whole sequence)
        const float4* s4 = (const float4*)P.x;
        for (int i = gtid; i < TT * BB * DD / 4; i += gsz) {
            float4 v = s4[i];
            float f[4] = {v.x, v.y, v.z, v.w};
            #pragma unroll
            for (int q = 0; q < 4; q++)
                bsplit(f[q], &g_xh[4 * i + q], &g_xl[4 * i + q]);
        }
    }
    {   // split stage3 weights
        const float* Wsrc[4] = {P.fwih[0], P.fwhh[0], P.fwih[1], P.fwhh[1]};
        #pragma unroll
        for (int mtx = 0; mtx < 4; mtx++) {
            const float4* s4 = (const float4*)Wsrc[mtx];
            __nv_bfloat16* dh = &g_wh[mtx >> 1][mtx & 1][0];
            __nv_bfloat16* dl = &g_wl[mtx >> 1][mtx & 1][0];
            for (int i = gtid; i < NG4 * DD / 4; i += gsz) {
                float4 v = s4[i];
                float f[4] = {v.x, v.y, v.z, v.w};
                #pragma unroll
                for (int q = 0; q < 4; q++)
                    bsplit(f[q], &dh[4 * i + q], &dl[4 * i + q]);
            }
        }
    }
    {   // split pw
        #pragma unroll
        for (int l = 0; l < 2; l++) {
            const float4* s4 = (const float4*)P.pw[l];
            for (int i = gtid; i < 14336 * 128 / 4; i += gsz) {
                float4 v = s4[i];
                float f[4] = {v.x, v.y, v.z, v.w};
                #pragma unroll
                for (int q = 0; q < 4; q++)
                    bsplit(f[q], &g_pwh[l][4 * i + q], &g_pwl[l][4 * i + q]);
            }
        }
    }
    {   // build composite stage1 weights
        #pragma unroll
        for (int l = 0; l < 2; l++) {
            const float* wih = P.awih[l];
            const float* whh = P.awhh[l];
            for (int i = gtid; i < 512 * KT1; i += gsz) {
                int n = i / KT1, k = i - n * KT1;
                float v = (k < AIN) ? wih[(size_t)n * AIN + k]
                                    : whh[n * AA + (k - AIN)];
                bsplit(v, &g_w1h[l][i], &g_w1l[l][i]);
            }
        }
    }
    grid_sync(gen);

    s1_prefetchW(0, sm);

    for (int t = 0; t < TT; t++) {
        const int p = t & 1;
        #pragma unroll
        for (int l = 0; l < NL; l++) {
            const __nv_bfloat16* xh = (l == 0) ? g_xh + (size_t)t * BB * DD
                                               : g_fhh[p ^ 1][0];
            const __nv_bfloat16* xl = (l == 0) ? g_xl + (size_t)t * BB * DD
                                               : g_fhl[p ^ 1][0];
            stage1_gemm(l, p, sm, xh, xl);
            s2_prefetchW(l, sm);                 // hides behind barrier + s1_point
            grid_sync(gen);
            s1_point(l, p, P.abih[l], P.abhh[l]);
            grid_sync(gen);
            const float* xc = (l == 0) ? P.x + (size_t)t * BB * DD
                                       : s_fh[p ^ 1][0];
            stage2(l, p, xc, P.pb[l], P.fb[l], sm);
            s3_prefetchW(l, sm);
            grid_sync(gen);
            stage3_gemm(l, sm);
            grid_sync(gen);                      // REQUIRED: s_pt cross-CTA dep
            s1_prefetchW(l ^ 1, sm);
            stage3b(l, p, t, P.out);
            grid_sync(gen);
        }
    }
    cp_wait0();
}

// ---------------- host launch ----------------------------------------------
extern "C" void kernel_launch(void* const* d_in, const int* in_sizes, int n_in,
                              void* d_out, int out_size)
{
    Params P;
    P.x       = (const float*)d_in[0];
    P.awih[0] = (const float*)d_in[1];  P.awih[1] = (const float*)d_in[10];
    P.awhh[0] = (const float*)d_in[2];  P.awhh[1] = (const float*)d_in[11];
    P.abih[0] = (const float*)d_in[3];  P.abih[1] = (const float*)d_in[12];
    P.abhh[0] = (const float*)d_in[4];  P.abhh[1] = (const float*)d_in[13];
    P.pw[0]   = (const float*)d_in[5];  P.pw[1]   = (const float*)d_in[14];
    P.pb[0]   = (const float*)d_in[6];  P.pb[1]   = (const float*)d_in[15];
    P.fwih[0] = (const float*)d_in[7];  P.fwih[1] = (const float*)d_in[16];
    P.fwhh[0] = (const float*)d_in[8];  P.fwhh[1] = (const float*)d_in[17];
    P.fb[0]   = (const float*)d_in[9];  P.fb[1]   = (const float*)d_in[18];
    P.out     = (float*)d_out;

    cudaFuncSetAttribute(alstm_persistent,
                         cudaFuncAttributeMaxDynamicSharedMemorySize,
                         SMEM_BYTES);
    alstm_persistent<<<NCTA, NTHR, SMEM_BYTES>>>(P);
}